// round 12
// baseline (speedup 1.0000x reference)
#include <cuda_runtime.h>
#include <cuda_fp16.h>
#include <math.h>

#define BB    64
#define DD    256
#define HEADS 8
#define DH    32
#define NTOK  625
#define NTOKP 640
#define NPAD  640
#define NBH   (BB*HEADS)

// ---- scratch (device globals, zero-initialized) ----
__device__ __align__(128) unsigned g_xh[(size_t)BB*NTOKP*128];   // x single fp16 words
__device__ __align__(128) unsigned g_wqh[768*128];               // w_qkv hi
__device__ __align__(128) unsigned g_wql[768*128];               // w_qkv lo
__device__ __align__(128) unsigned g_woh[256*128];               // w_out single
__device__ __align__(128) unsigned g_qh[(size_t)NBH*NTOKP*16];   // Q hi
__device__ __align__(128) unsigned g_ql[(size_t)NBH*NTOKP*16];   // Q lo
__device__ __align__(128) unsigned g_kh[(size_t)NBH*NTOKP*16];   // K single
__device__ __align__(128) float    g_v [(size_t)NBH*NTOK*DH];
__device__ __align__(128) unsigned g_vth[(size_t)NBH*32*320];    // V^T hi
__device__ __align__(128) unsigned g_vtl[(size_t)NBH*32*320];    // V^T lo
__device__ __align__(128) unsigned g_oh[(size_t)BB*NTOKP*128];   // O hi
__device__ __align__(128) unsigned g_ol[(size_t)BB*NTOKP*128];   // O lo
__device__ __align__(16)  float    g_bias[HEADS*NPAD*NPAD];

// ================= fp16 pack/split helpers =================
__device__ __forceinline__ unsigned packhf(float x0, float x1) {
    unsigned u;
    asm("cvt.rn.f16x2.f32 %0, %1, %2;" : "=r"(u) : "f"(x1), "f"(x0));
    return u;
}
__device__ __forceinline__ void splith2(float x0, float x1,
                                        unsigned &h, unsigned &l) {
    h = packhf(x0, x1);
    __half2 hh = *reinterpret_cast<__half2*>(&h);
    l = packhf(x0 - __low2float(hh), x1 - __high2float(hh));
}
__device__ __forceinline__ void mma16(float4 &d, const unsigned a[4],
                                      unsigned b0, unsigned b1) {
    asm volatile(
        "mma.sync.aligned.m16n8k16.row.col.f32.f16.f16.f32 "
        "{%0,%1,%2,%3}, {%4,%5,%6,%7}, {%8,%9}, {%0,%1,%2,%3};"
        : "+f"(d.x), "+f"(d.y), "+f"(d.z), "+f"(d.w)
        : "r"(a[0]), "r"(a[1]), "r"(a[2]), "r"(a[3]), "r"(b0), "r"(b1));
}
// ================= ldmatrix / cp.async helpers =================
__device__ __forceinline__ unsigned sptr(const void* p) {
    return (unsigned)__cvta_generic_to_shared(p);
}
__device__ __forceinline__ void ldsm4(unsigned r[4], unsigned addr) {
    asm volatile("ldmatrix.sync.aligned.m8n8.x4.shared.b16 {%0,%1,%2,%3}, [%4];"
        : "=r"(r[0]), "=r"(r[1]), "=r"(r[2]), "=r"(r[3]) : "r"(addr));
}
__device__ __forceinline__ void cpa16(unsigned dst, const void* src) {
    asm volatile("cp.async.cg.shared.global [%0], [%1], 16;" :: "r"(dst), "l"(src));
}
#define CP_COMMIT() asm volatile("cp.async.commit_group;")
#define CP_WAIT0()  asm volatile("cp.async.wait_group 0;")

// ============================================================
// Kernel 0: bias_fill
// ============================================================
__global__ void bias_fill(const float* __restrict__ table,
                          const int*   __restrict__ rel) {
    int idx = blockIdx.x * blockDim.x + threadIdx.x;
    const int total = HEADS * NTOK * NTOK;
    if (idx >= total) return;
    int h = idx / (NTOK * NTOK);
    int r = idx - h * (NTOK * NTOK);
    int i = r / NTOK;
    int j = r - i * NTOK;
    g_bias[(h * NPAD + i) * NPAD + j] = table[rel[r] * HEADS + h];
}

// ============================================================
// prep_w: w_qkv split (h+l), w_out single fp16
// ============================================================
__global__ void prep_w(const float* __restrict__ wq,
                       const float* __restrict__ wo) {
    int idx = blockIdx.x * 256 + threadIdx.x;
    if (idx < 768 * 128) {
        int k2 = idx / 768, n = idx - k2 * 768;
        splith2(wq[(size_t)(2*k2) * 768 + n], wq[(size_t)(2*k2+1) * 768 + n],
                g_wqh[n*128 + k2], g_wql[n*128 + k2]);
    } else {
        int j = idx - 768 * 128;
        if (j < 256 * 128) {
            int k2 = j / 256, n = j - k2 * 256;
            g_woh[n*128 + k2] = packhf(wo[(size_t)(2*k2) * 256 + n],
                                       wo[(size_t)(2*k2+1) * 256 + n]);
        }
    }
}

// ============================================================
// prep_x: transpose x (b,k,p) -> single fp16 words (b,p,[k2])
// ============================================================
__global__ __launch_bounds__(256) void prep_x(const float* __restrict__ x) {
    __shared__ float sm[64][65];
    int p0 = blockIdx.x * 64, k0 = blockIdx.y * 64, b = blockIdx.z;
    int t = threadIdx.x;
    int pp = t & 63, kk0 = t >> 6;
    const float* xb = x + ((size_t)b * DD + k0) * NTOK + p0;
    bool pok = (p0 + pp) < NTOK;
    #pragma unroll
    for (int i = 0; i < 16; i++) {
        int kk = kk0 + i * 4;
        sm[kk][pp] = pok ? xb[(size_t)kk * NTOK + pp] : 0.f;
    }
    __syncthreads();
    int row = t >> 2, wseg = t & 3;
    unsigned hw[8];
    #pragma unroll
    for (int i = 0; i < 8; i++) {
        int j2 = wseg * 8 + i;
        hw[i] = packhf(sm[2*j2][row], sm[2*j2+1][row]);
    }
    size_t base = ((size_t)b * NTOKP + p0 + row) * 128 + k0/2 + wseg*8;
    *(uint4*)&g_xh[base]     = *(uint4*)&hw[0];
    *(uint4*)&g_xh[base + 4] = *(uint4*)&hw[4];
}

// ============================================================
// prep_vt: transpose+split V (bh,j,e) -> (bh,e,[j2]) fp16 h/l
// ============================================================
__global__ __launch_bounds__(256) void prep_vt() {
    __shared__ float sm[64][36];
    int jt = blockIdx.x, bh = blockIdx.y;
    int j0 = jt * 64, t = threadIdx.x;
    int j = t >> 2, e0 = (t & 3) * 8;
    const float* vb = g_v + (size_t)bh * NTOK * DH;
    if (j0 + j < NTOK) {
        *(float4*)&sm[j][e0]     = *(const float4*)&vb[(size_t)(j0+j) * DH + e0];
        *(float4*)&sm[j][e0 + 4] = *(const float4*)&vb[(size_t)(j0+j) * DH + e0 + 4];
    } else {
        #pragma unroll
        for (int i = 0; i < 8; i++) sm[j][e0 + i] = 0.f;
    }
    __syncthreads();
    int e = t >> 3, wseg = t & 7;
    unsigned hw[4], lw[4];
    #pragma unroll
    for (int i = 0; i < 4; i++) {
        int j2 = wseg * 4 + i;
        splith2(sm[2*j2][e], sm[2*j2+1][e], hw[i], lw[i]);
    }
    size_t base = ((size_t)bh * 32 + e) * 320 + jt*32 + wseg*4;
    *(uint4*)&g_vth[base] = *(uint4*)hw;
    *(uint4*)&g_vtl[base] = *(uint4*)lw;
}

// ============================================================
// Kernel 1: QKV projection. A=x single fp16, B=w split (2-term).
// hi-pass then lo-pass over all 8 accs (acc RAW distance 8).
// ============================================================
#define STG_Q 5120
#define QKV_SMEM (2*STG_Q*4)   // 40960 B

__global__ __launch_bounds__(256, 3) void qkv_mma() {
    extern __shared__ __align__(16) unsigned qsm[];
    int b  = blockIdx.z;
    int p0 = blockIdx.x * 128;
    int n0 = blockIdx.y * 64;
    int tid = threadIdx.x;
    int wid = tid >> 5, lane = tid & 31;
    int wm = wid & 3, wn = wid >> 2;
    int r = lane >> 2, c = lane & 3;
    unsigned smb = sptr(qsm);

    float4 acc[2][4];
    #pragma unroll
    for (int i = 0; i < 2; i++)
        #pragma unroll
        for (int j = 0; j < 4; j++) acc[i][j] = make_float4(0,0,0,0);

    int aRow = lane & 15;
    int aSel = (lane >> 4) * 4;
    int bRow = ((lane >> 4) << 3) | (lane & 7);
    int bSel = ((lane >> 3) & 1) * 4;

    int caRow = tid >> 1, caHalf = tid & 1;
    int cbRow = tid >> 2, cbSeg = tid & 3;
    size_t aSrc = ((size_t)b * NTOKP + p0 + caRow) * 128 + caHalf * 8;
    size_t bSrc = (size_t)(n0 + cbRow) * 128 + cbSeg * 4;

    auto copy_slab = [&](int slab, int buf) {
        unsigned sb = smb + buf * STG_Q * 4;
        unsigned dA = sb + (caRow*20 + caHalf*8) * 4;
        const unsigned* sh = g_xh + aSrc + slab*16;
        cpa16(dA,      sh);
        cpa16(dA + 16, sh + 4);
        unsigned dB = sb + (2560 + cbRow*20 + cbSeg*4) * 4;
        cpa16(dB,          g_wqh + bSrc + slab*16);
        cpa16(dB + 1280*4, g_wql + bSrc + slab*16);
    };

    copy_slab(0, 0);
    CP_COMMIT();
    int buf = 0;
    for (int s = 0; s < 8; s++) {
        CP_WAIT0();
        __syncthreads();
        if (s < 7) { copy_slab(s + 1, buf ^ 1); CP_COMMIT(); }

        unsigned AhB = smb + buf * STG_Q * 4;
        unsigned BhB = AhB + 2560 * 4;
        unsigned BlB = AhB + 3840 * 4;
        #pragma unroll
        for (int ktl = 0; ktl < 2; ktl++) {
            unsigned ah[2][4];
            #pragma unroll
            for (int mt = 0; mt < 2; mt++) {
                unsigned off = ((wm*32 + mt*16 + aRow) * 20 + ktl*8 + aSel) * 4u;
                ldsm4(ah[mt], AhB + off);
            }
            unsigned bhf[4][2], blf[4][2];
            #pragma unroll
            for (int ntp = 0; ntp < 2; ntp++) {
                unsigned off = ((wn*32 + ntp*16 + bRow) * 20 + ktl*8 + bSel) * 4u;
                unsigned t4[4];
                ldsm4(t4, BhB + off);
                bhf[2*ntp][0] = t4[0]; bhf[2*ntp][1] = t4[1];
                bhf[2*ntp+1][0] = t4[2]; bhf[2*ntp+1][1] = t4[3];
                ldsm4(t4, BlB + off);
                blf[2*ntp][0] = t4[0]; blf[2*ntp][1] = t4[1];
                blf[2*ntp+1][0] = t4[2]; blf[2*ntp+1][1] = t4[3];
            }
            // hi pass (8 independent accs), then lo pass
            #pragma unroll
            for (int nt = 0; nt < 4; nt++)
                #pragma unroll
                for (int mt = 0; mt < 2; mt++)
                    mma16(acc[mt][nt], ah[mt], bhf[nt][0], bhf[nt][1]);
            #pragma unroll
            for (int nt = 0; nt < 4; nt++)
                #pragma unroll
                for (int mt = 0; mt < 2; mt++)
                    mma16(acc[mt][nt], ah[mt], blf[nt][0], blf[nt][1]);
        }
        buf ^= 1;
    }

    // epilogue: Q split fp16, K single fp16, V fp32
    #pragma unroll
    for (int nt = 0; nt < 4; nt++) {
        int ng0 = n0 + wn * 32 + nt * 8 + 2 * c;
        int which = ng0 >> 8;
        int h = (ng0 >> 5) & 7;
        int e = ng0 & 31;
        int bhI = b * HEADS + h;
        #pragma unroll
        for (int mt = 0; mt < 2; mt++) {
            int p = p0 + wm * 32 + mt * 16 + r;
            float4 a = acc[mt][nt];
            if (which == 2) {
                if (p < NTOK)
                    *(float2*)&g_v[((size_t)bhI*NTOK + p)*DH + e] = make_float2(a.x, a.y);
                if (p + 8 < NTOK)
                    *(float2*)&g_v[((size_t)bhI*NTOK + p + 8)*DH + e] = make_float2(a.z, a.w);
            } else if (which == 0) {
                const float s = 0.17677669529663687f;
                size_t base = (size_t)bhI * NTOKP * 16 + (e >> 1);
                if (p < NTOK) {
                    unsigned hw, lw; splith2(a.x*s, a.y*s, hw, lw);
                    g_qh[base + (size_t)p*16] = hw; g_ql[base + (size_t)p*16] = lw;
                }
                if (p + 8 < NTOK) {
                    unsigned hw, lw; splith2(a.z*s, a.w*s, hw, lw);
                    g_qh[base + (size_t)(p+8)*16] = hw; g_ql[base + (size_t)(p+8)*16] = lw;
                }
            } else {
                size_t base = (size_t)bhI * NTOKP * 16 + (e >> 1);
                if (p < NTOK)
                    g_kh[base + (size_t)p*16] = packhf(a.x, a.y);
                if (p + 8 < NTOK)
                    g_kh[base + (size_t)(p+8)*16] = packhf(a.z, a.w);
            }
        }
    }
}

// ============================================================
// Kernel 2: flash attention. S: load K tiles first, qh-pass then
// ql-pass. PV: load V tiles first, hi-pass then lo-pass.
// ============================================================
__global__ __launch_bounds__(256, 2) void attn_mma() {
    __shared__ __align__(16) unsigned Kh[2][64][20];
    __shared__ __align__(16) unsigned Vh[2][32][36], Vl[2][32][36];

    int tid = threadIdx.x;
    int wid = tid >> 5, lane = tid & 31;
    int r = lane >> 2, c = lane & 3;

    int q0 = blockIdx.x * 128;
    int bh = blockIdx.y;
    int h = bh & 7;

    int bRow = ((lane >> 4) << 3) | (lane & 7);
    int bSel = ((lane >> 3) & 1) * 4;

    int ckRow = tid >> 2, ckSeg = tid & 3;
    int cvRow = tid >> 3, cvSeg = tid & 7;
    size_t kSrc = ((size_t)bh * NTOKP + ckRow) * 16 + ckSeg * 4;
    size_t vSrc = ((size_t)bh * 32 + cvRow) * 320 + cvSeg * 4;

    auto copy_tile = [&](int jt, int buf) {
        cpa16(sptr(&Kh[buf][ckRow][ckSeg*4]), g_kh + kSrc + (size_t)jt*64*16);
        cpa16(sptr(&Vh[buf][cvRow][cvSeg*4]), g_vth + vSrc + jt*32);
        cpa16(sptr(&Vl[buf][cvRow][cvSeg*4]), g_vtl + vSrc + jt*32);
    };

    // Q fragments: pre-split fp16 words
    unsigned qh[2][4], ql[2][4];
    {
        const unsigned* qbh = g_qh + (size_t)bh * NTOKP * 16;
        const unsigned* qbl = g_ql + (size_t)bh * NTOKP * 16;
        int pr = q0 + wid * 16 + r;
        #pragma unroll
        for (int kt = 0; kt < 2; kt++) {
            qh[kt][0] = qbh[(size_t)pr*16     + kt*8 + c];
            qh[kt][1] = qbh[(size_t)(pr+8)*16 + kt*8 + c];
            qh[kt][2] = qbh[(size_t)pr*16     + kt*8 + c + 4];
            qh[kt][3] = qbh[(size_t)(pr+8)*16 + kt*8 + c + 4];
            ql[kt][0] = qbl[(size_t)pr*16     + kt*8 + c];
            ql[kt][1] = qbl[(size_t)(pr+8)*16 + kt*8 + c];
            ql[kt][2] = qbl[(size_t)pr*16     + kt*8 + c + 4];
            ql[kt][3] = qbl[(size_t)(pr+8)*16 + kt*8 + c + 4];
        }
    }

    float4 O[4];
    #pragma unroll
    for (int i = 0; i < 4; i++) O[i] = make_float4(0,0,0,0);
    float m0 = -INFINITY, m1 = -INFINITY, l0 = 0.f, l1 = 0.f;

    copy_tile(0, 0);
    CP_COMMIT();
    int buf = 0;
    for (int jt = 0; jt < 10; jt++) {
        int j0 = jt * 64;
        CP_WAIT0();
        __syncthreads();
        if (jt < 9) { copy_tile(jt + 1, buf ^ 1); CP_COMMIT(); }

        unsigned KhB = sptr(Kh) + buf * 64*20*4;
        unsigned VhB = sptr(Vh) + buf * 32*36*4;
        unsigned VlB = sptr(Vl) + buf * 32*36*4;

        // ---- S = Q K^T : load all K frags, then qh pass, then ql pass ----
        float4 acc[8];
        #pragma unroll
        for (int i = 0; i < 8; i++) acc[i] = make_float4(0,0,0,0);
        #pragma unroll
        for (int kt = 0; kt < 2; kt++) {
            unsigned th[4][4];
            #pragma unroll
            for (int ntp = 0; ntp < 4; ntp++) {
                unsigned off = ((ntp*16 + bRow) * 20 + kt*8 + bSel) * 4u;
                ldsm4(th[ntp], KhB + off);
            }
            #pragma unroll
            for (int ntp = 0; ntp < 4; ntp++) {
                mma16(acc[2*ntp  ], qh[kt], th[ntp][0], th[ntp][1]);
                mma16(acc[2*ntp+1], qh[kt], th[ntp][2], th[ntp][3]);
            }
            #pragma unroll
            for (int ntp = 0; ntp < 4; ntp++) {
                mma16(acc[2*ntp  ], ql[kt], th[ntp][0], th[ntp][1]);
                mma16(acc[2*ntp+1], ql[kt], th[ntp][2], th[ntp][3]);
            }
        }

        // ---- bias + tail mask ----
        {
            const float* bp = g_bias + ((size_t)(h * NPAD + q0 + wid*16 + r)) * NPAD + j0;
            #pragma unroll
            for (int nt = 0; nt < 8; nt++) {
                float2 b0v = *(const float2*)&bp[nt*8 + 2*c];
                float2 b1v = *(const float2*)&bp[8*NPAD + nt*8 + 2*c];
                acc[nt].x += b0v.x; acc[nt].y += b0v.y;
                acc[nt].z += b1v.x; acc[nt].w += b1v.y;
            }
            if (j0 + 64 > NTOK) {
                #pragma unroll
                for (int nt = 0; nt < 8; nt++) {
                    int jc = j0 + nt*8 + 2*c;
                    if (jc     >= NTOK) { acc[nt].x = -1e30f; acc[nt].z = -1e30f; }
                    if (jc + 1 >= NTOK) { acc[nt].y = -1e30f; acc[nt].w = -1e30f; }
                }
            }
        }

        // ---- online softmax (quad reduce) ----
        float t0 = -INFINITY, t1 = -INFINITY;
        #pragma unroll
        for (int nt = 0; nt < 8; nt++) {
            t0 = fmaxf(t0, fmaxf(acc[nt].x, acc[nt].y));
            t1 = fmaxf(t1, fmaxf(acc[nt].z, acc[nt].w));
        }
        #pragma unroll
        for (int off = 1; off <= 2; off <<= 1) {
            t0 = fmaxf(t0, __shfl_xor_sync(0xffffffffu, t0, off));
            t1 = fmaxf(t1, __shfl_xor_sync(0xffffffffu, t1, off));
        }
        float mn0 = fmaxf(m0, t0), mn1 = fmaxf(m1, t1);
        float cor0 = __expf(m0 - mn0), cor1 = __expf(m1 - mn1);
        float s0 = 0.f, s1 = 0.f;
        #pragma unroll
        for (int nt = 0; nt < 8; nt++) {
            acc[nt].x = __expf(acc[nt].x - mn0);
            acc[nt].y = __expf(acc[nt].y - mn0);
            acc[nt].z = __expf(acc[nt].z - mn1);
            acc[nt].w = __expf(acc[nt].w - mn1);
            s0 += acc[nt].x + acc[nt].y;
            s1 += acc[nt].z + acc[nt].w;
        }
        #pragma unroll
        for (int off = 1; off <= 2; off <<= 1) {
            s0 += __shfl_xor_sync(0xffffffffu, s0, off);
            s1 += __shfl_xor_sync(0xffffffffu, s1, off);
        }
        l0 = l0 * cor0 + s0;  m0 = mn0;
        l1 = l1 * cor1 + s1;  m1 = mn1;
        #pragma unroll
        for (int i = 0; i < 4; i++) {
            O[i].x *= cor0; O[i].y *= cor0;
            O[i].z *= cor1; O[i].w *= cor1;
        }

        // ---- O += P V : load V frags, hi pass over 4 Os, lo pass ----
        #pragma unroll
        for (int kt = 0; kt < 4; kt++) {
            unsigned ph[4];
            ph[0] = packhf(acc[2*kt  ].x, acc[2*kt  ].y);
            ph[1] = packhf(acc[2*kt  ].z, acc[2*kt  ].w);
            ph[2] = packhf(acc[2*kt+1].x, acc[2*kt+1].y);
            ph[3] = packhf(acc[2*kt+1].z, acc[2*kt+1].w);
            unsigned th[2][4], tl[2][4];
            #pragma unroll
            for (int ntp = 0; ntp < 2; ntp++) {
                unsigned off = ((ntp*16 + bRow) * 36 + kt*8 + bSel) * 4u;
                ldsm4(th[ntp], VhB + off);
                ldsm4(tl[ntp], VlB + off);
            }
            #pragma unroll
            for (int ntp = 0; ntp < 2; ntp++) {
                mma16(O[2*ntp  ], ph, th[ntp][0], th[ntp][1]);
                mma16(O[2*ntp+1], ph, th[ntp][2], th[ntp][3]);
            }
            #pragma unroll
            for (int ntp = 0; ntp < 2; ntp++) {
                mma16(O[2*ntp  ], ph, tl[ntp][0], tl[ntp][1]);
                mma16(O[2*ntp+1], ph, tl[ntp][2], tl[ntp][3]);
            }
        }
        buf ^= 1;
    }

    // epilogue: O split fp16 -> g_oh/g_ol (b, p, [word])
    float inv0 = 1.f / l0, inv1 = 1.f / l1;
    size_t ob = (size_t)(bh >> 3) * NTOKP * 128 + h * 16;
    #pragma unroll
    for (int nt = 0; nt < 4; nt++) {
        int w2 = nt * 4 + c;
        int p = q0 + wid * 16 + r;
        if (p < NTOK) {
            unsigned hw, lw; splith2(O[nt].x * inv0, O[nt].y * inv0, hw, lw);
            g_oh[ob + (size_t)p*128 + w2] = hw;
            g_ol[ob + (size_t)p*128 + w2] = lw;
        }
        if (p + 8 < NTOK) {
            unsigned hw, lw; splith2(O[nt].z * inv1, O[nt].w * inv1, hw, lw);
            g_oh[ob + (size_t)(p+8)*128 + w2] = hw;
            g_ol[ob + (size_t)(p+8)*128 + w2] = lw;
        }
    }
}

// ============================================================
// Kernel 3: output projection. A=O split, B=w_out single.
// hi-pass (ah) then lo-pass (al) over all 8 accs.
// ============================================================
#define STG_O 6400
#define OUT_SMEM (2*STG_O*4)   // 51200 B

__global__ __launch_bounds__(256, 3) void out_mma(float* __restrict__ out) {
    extern __shared__ __align__(16) unsigned osm[];
    float (*Cs)[69] = (float(*)[69])osm;

    int b  = blockIdx.z;
    int p0 = blockIdx.x * 128;
    int n0 = blockIdx.y * 64;
    int tid = threadIdx.x;
    int wid = tid >> 5, lane = tid & 31;
    int wm = wid & 3, wn = wid >> 2;
    int r = lane >> 2, c = lane & 3;
    unsigned smb = sptr(osm);

    float4 acc[2][4];
    #pragma unroll
    for (int i = 0; i < 2; i++)
        #pragma unroll
        for (int j = 0; j < 4; j++) acc[i][j] = make_float4(0,0,0,0);

    int aRow = lane & 15;
    int aSel = (lane >> 4) * 4;
    int bRow = ((lane >> 4) << 3) | (lane & 7);
    int bSel = ((lane >> 3) & 1) * 4;

    int caRow = tid >> 1, caHalf = tid & 1;
    int cbRow = tid >> 2, cbSeg = tid & 3;
    size_t aSrc = ((size_t)b * NTOKP + p0 + caRow) * 128 + caHalf * 8;
    size_t bSrc = (size_t)(n0 + cbRow) * 128 + cbSeg * 4;

    auto copy_slab = [&](int slab, int buf) {
        unsigned sb = smb + buf * STG_O * 4;
        unsigned dA  = sb + (caRow*20 + caHalf*8) * 4;
        unsigned dAl = dA + 2560 * 4;
        const unsigned* sh = g_oh + aSrc + slab*16;
        const unsigned* sl = g_ol + aSrc + slab*16;
        cpa16(dA,       sh);  cpa16(dA  + 16, sh + 4);
        cpa16(dAl,      sl);  cpa16(dAl + 16, sl + 4);
        unsigned dB = sb + (5120 + cbRow*20 + cbSeg*4) * 4;
        cpa16(dB, g_woh + bSrc + slab*16);
    };

    copy_slab(0, 0);
    CP_COMMIT();
    int buf = 0;
    for (int s = 0; s < 8; s++) {
        CP_WAIT0();
        __syncthreads();
        if (s < 7) { copy_slab(s + 1, buf ^ 1); CP_COMMIT(); }

        unsigned AhB = smb + buf * STG_O * 4;
        unsigned AlB = AhB + 2560 * 4;
        unsigned BhB = AhB + 5120 * 4;
        #pragma unroll
        for (int ktl = 0; ktl < 2; ktl++) {
            unsigned ah[2][4], al[2][4];
            #pragma unroll
            for (int mt = 0; mt < 2; mt++) {
                unsigned off = ((wm*32 + mt*16 + aRow) * 20 + ktl*8 + aSel) * 4u;
                ldsm4(ah[mt], AhB + off);
                ldsm4(al[mt], AlB + off);
            }
            unsigned bhf[4][2];
            #pragma unroll
            for (int ntp = 0; ntp < 2; ntp++) {
                unsigned off = ((wn*32 + ntp*16 + bRow) * 20 + ktl*8 + bSel) * 4u;
                unsigned t4[4];
                ldsm4(t4, BhB + off);
                bhf[2*ntp][0] = t4[0]; bhf[2*ntp][1] = t4[1];
                bhf[2*ntp+1][0] = t4[2]; bhf[2*ntp+1][1] = t4[3];
            }
            // hi pass then lo pass
            #pragma unroll
            for (int nt = 0; nt < 4; nt++)
                #pragma unroll
                for (int mt = 0; mt < 2; mt++)
                    mma16(acc[mt][nt], ah[mt], bhf[nt][0], bhf[nt][1]);
            #pragma unroll
            for (int nt = 0; nt < 4; nt++)
                #pragma unroll
                for (int mt = 0; mt < 2; mt++)
                    mma16(acc[mt][nt], al[mt], bhf[nt][0], bhf[nt][1]);
        }
        buf ^= 1;
    }

    __syncthreads();   // staging done before Cs reuse

    #pragma unroll
    for (int mt = 0; mt < 2; mt++) {
        int m = wm * 32 + mt * 16 + r;
        #pragma unroll
        for (int nt = 0; nt < 4; nt++) {
            int n = wn * 32 + nt * 8 + 2 * c;
            Cs[m    ][n    ] = acc[mt][nt].x;
            Cs[m    ][n + 1] = acc[mt][nt].y;
            Cs[m + 8][n    ] = acc[mt][nt].z;
            Cs[m + 8][n + 1] = acc[mt][nt].w;
        }
    }
    __syncthreads();

    #pragma unroll
    for (int it = 0; it < 32; it++) {
        int idx = it * 256 + tid;
        int n = idx >> 7;
        int m = idx & 127;
        int p = p0 + m;
        if (p < NTOK)
            out[((size_t)b * DD + n0 + n) * NTOK + p] = Cs[m][n];
    }
}

// ============================================================
extern "C" void kernel_launch(void* const* d_in, const int* in_sizes, int n_in,
                              void* d_out, int out_size) {
    const float* x          = (const float*)d_in[0];
    const float* w_qkv      = (const float*)d_in[1];
    const float* w_out      = (const float*)d_in[2];
    const float* bias_table = (const float*)d_in[3];
    const int*   rel        = (const int*)d_in[4];
    float* out = (float*)d_out;

    cudaFuncSetAttribute(qkv_mma, cudaFuncAttributeMaxDynamicSharedMemorySize,
                         QKV_SMEM);
    cudaFuncSetAttribute(out_mma, cudaFuncAttributeMaxDynamicSharedMemorySize,
                         OUT_SMEM);

    bias_fill<<<(HEADS * NTOK * NTOK + 255) / 256, 256>>>(bias_table, rel);
    prep_w<<<512, 256>>>(w_qkv, w_out);
    prep_x<<<dim3(10, 4, BB), 256>>>(x);
    qkv_mma<<<dim3(5, 12, BB), 256, QKV_SMEM>>>();
    prep_vt<<<dim3(10, NBH), 256>>>();
    attn_mma<<<dim3(5, NBH), 256>>>();
    out_mma<<<dim3(5, 4, BB), 256, OUT_SMEM>>>(out);
}

// round 14
// speedup vs baseline: 1.0101x; 1.0101x over previous
#include <cuda_runtime.h>
#include <cuda_fp16.h>
#include <math.h>

#define BB    64
#define DD    256
#define HEADS 8
#define DH    32
#define NTOK  625
#define NTOKP 640
#define NPAD  640
#define NBH   (BB*HEADS)

// ---- scratch (device globals, zero-initialized) ----
__device__ __align__(128) unsigned g_xh[(size_t)BB*NTOKP*128];   // x single fp16 words
__device__ __align__(128) unsigned g_wqh[768*128];               // w_qkv hi
__device__ __align__(128) unsigned g_wql[768*128];               // w_qkv lo
__device__ __align__(128) unsigned g_woh[256*128];               // w_out single
__device__ __align__(128) unsigned g_qh[(size_t)NBH*NTOKP*16];   // Q hi
__device__ __align__(128) unsigned g_ql[(size_t)NBH*NTOKP*16];   // Q lo
__device__ __align__(128) unsigned g_kh[(size_t)NBH*NTOKP*16];   // K single
__device__ __align__(128) float    g_v [(size_t)NBH*NTOK*DH];
__device__ __align__(128) unsigned g_vth[(size_t)NBH*32*320];    // V^T hi
__device__ __align__(128) unsigned g_vtl[(size_t)NBH*32*320];    // V^T lo
__device__ __align__(128) unsigned g_oh[(size_t)BB*NTOKP*128];   // O hi
__device__ __align__(128) unsigned g_ol[(size_t)BB*NTOKP*128];   // O lo
__device__ __align__(16)  float    g_bias[HEADS*NPAD*NPAD];

// ================= fp16 pack/split helpers =================
__device__ __forceinline__ unsigned packhf(float x0, float x1) {
    unsigned u;
    asm("cvt.rn.f16x2.f32 %0, %1, %2;" : "=r"(u) : "f"(x1), "f"(x0));
    return u;
}
__device__ __forceinline__ void splith2(float x0, float x1,
                                        unsigned &h, unsigned &l) {
    h = packhf(x0, x1);
    __half2 hh = *reinterpret_cast<__half2*>(&h);
    l = packhf(x0 - __low2float(hh), x1 - __high2float(hh));
}
__device__ __forceinline__ void mma16(float4 &d, const unsigned a[4],
                                      unsigned b0, unsigned b1) {
    asm volatile(
        "mma.sync.aligned.m16n8k16.row.col.f32.f16.f16.f32 "
        "{%0,%1,%2,%3}, {%4,%5,%6,%7}, {%8,%9}, {%0,%1,%2,%3};"
        : "+f"(d.x), "+f"(d.y), "+f"(d.z), "+f"(d.w)
        : "r"(a[0]), "r"(a[1]), "r"(a[2]), "r"(a[3]), "r"(b0), "r"(b1));
}
// ================= ldmatrix / cp.async helpers =================
__device__ __forceinline__ unsigned sptr(const void* p) {
    return (unsigned)__cvta_generic_to_shared(p);
}
__device__ __forceinline__ void ldsm4(unsigned r[4], unsigned addr) {
    asm volatile("ldmatrix.sync.aligned.m8n8.x4.shared.b16 {%0,%1,%2,%3}, [%4];"
        : "=r"(r[0]), "=r"(r[1]), "=r"(r[2]), "=r"(r[3]) : "r"(addr));
}
__device__ __forceinline__ void cpa16(unsigned dst, const void* src) {
    asm volatile("cp.async.cg.shared.global [%0], [%1], 16;" :: "r"(dst), "l"(src));
}
#define CP_COMMIT() asm volatile("cp.async.commit_group;")
#define CP_WAIT0()  asm volatile("cp.async.wait_group 0;")

// ============================================================
// Kernel 0: bias_fill
// ============================================================
__global__ void bias_fill(const float* __restrict__ table,
                          const int*   __restrict__ rel) {
    int idx = blockIdx.x * blockDim.x + threadIdx.x;
    const int total = HEADS * NTOK * NTOK;
    if (idx >= total) return;
    int h = idx / (NTOK * NTOK);
    int r = idx - h * (NTOK * NTOK);
    int i = r / NTOK;
    int j = r - i * NTOK;
    g_bias[(h * NPAD + i) * NPAD + j] = table[rel[r] * HEADS + h];
}

// ============================================================
// prep_w: w_qkv split (h+l), w_out single fp16
// ============================================================
__global__ void prep_w(const float* __restrict__ wq,
                       const float* __restrict__ wo) {
    int idx = blockIdx.x * 256 + threadIdx.x;
    if (idx < 768 * 128) {
        int k2 = idx / 768, n = idx - k2 * 768;
        splith2(wq[(size_t)(2*k2) * 768 + n], wq[(size_t)(2*k2+1) * 768 + n],
                g_wqh[n*128 + k2], g_wql[n*128 + k2]);
    } else {
        int j = idx - 768 * 128;
        if (j < 256 * 128) {
            int k2 = j / 256, n = j - k2 * 256;
            g_woh[n*128 + k2] = packhf(wo[(size_t)(2*k2) * 256 + n],
                                       wo[(size_t)(2*k2+1) * 256 + n]);
        }
    }
}

// ============================================================
// prep_x: transpose x (b,k,p) -> single fp16 words (b,p,[k2])
// ============================================================
__global__ __launch_bounds__(256) void prep_x(const float* __restrict__ x) {
    __shared__ float sm[64][65];
    int p0 = blockIdx.x * 64, k0 = blockIdx.y * 64, b = blockIdx.z;
    int t = threadIdx.x;
    int pp = t & 63, kk0 = t >> 6;
    const float* xb = x + ((size_t)b * DD + k0) * NTOK + p0;
    bool pok = (p0 + pp) < NTOK;
    #pragma unroll
    for (int i = 0; i < 16; i++) {
        int kk = kk0 + i * 4;
        sm[kk][pp] = pok ? xb[(size_t)kk * NTOK + pp] : 0.f;
    }
    __syncthreads();
    int row = t >> 2, wseg = t & 3;
    unsigned hw[8];
    #pragma unroll
    for (int i = 0; i < 8; i++) {
        int j2 = wseg * 8 + i;
        hw[i] = packhf(sm[2*j2][row], sm[2*j2+1][row]);
    }
    size_t base = ((size_t)b * NTOKP + p0 + row) * 128 + k0/2 + wseg*8;
    *(uint4*)&g_xh[base]     = *(uint4*)&hw[0];
    *(uint4*)&g_xh[base + 4] = *(uint4*)&hw[4];
}

// ============================================================
// prep_vt: transpose+split V (bh,j,e) -> (bh,e,[j2]) fp16 h/l
// ============================================================
__global__ __launch_bounds__(256) void prep_vt() {
    __shared__ float sm[64][36];
    int jt = blockIdx.x, bh = blockIdx.y;
    int j0 = jt * 64, t = threadIdx.x;
    int j = t >> 2, e0 = (t & 3) * 8;
    const float* vb = g_v + (size_t)bh * NTOK * DH;
    if (j0 + j < NTOK) {
        *(float4*)&sm[j][e0]     = *(const float4*)&vb[(size_t)(j0+j) * DH + e0];
        *(float4*)&sm[j][e0 + 4] = *(const float4*)&vb[(size_t)(j0+j) * DH + e0 + 4];
    } else {
        #pragma unroll
        for (int i = 0; i < 8; i++) sm[j][e0 + i] = 0.f;
    }
    __syncthreads();
    int e = t >> 3, wseg = t & 7;
    unsigned hw[4], lw[4];
    #pragma unroll
    for (int i = 0; i < 4; i++) {
        int j2 = wseg * 4 + i;
        splith2(sm[2*j2][e], sm[2*j2+1][e], hw[i], lw[i]);
    }
    size_t base = ((size_t)bh * 32 + e) * 320 + jt*32 + wseg*4;
    *(uint4*)&g_vth[base] = *(uint4*)hw;
    *(uint4*)&g_vtl[base] = *(uint4*)lw;
}

// ============================================================
// Kernel 1: QKV projection. A=x single fp16, B=w split (2-term).
// K-slab 64 (4 slabs): halves barrier count vs 32-slabs.
// Stage (words): A[128][36] @0 | Bh[64][36] @4608 | Bl @6912.
// ============================================================
#define STG_Q 9216
#define QKV_SMEM (2*STG_Q*4)   // 73728 B

__global__ __launch_bounds__(256, 3) void qkv_mma() {
    extern __shared__ __align__(16) unsigned qsm[];
    int b  = blockIdx.z;
    int p0 = blockIdx.x * 128;
    int n0 = blockIdx.y * 64;
    int tid = threadIdx.x;
    int wid = tid >> 5, lane = tid & 31;
    int wm = wid & 3, wn = wid >> 2;
    int r = lane >> 2, c = lane & 3;
    unsigned smb = sptr(qsm);

    float4 acc[2][4];
    #pragma unroll
    for (int i = 0; i < 2; i++)
        #pragma unroll
        for (int j = 0; j < 4; j++) acc[i][j] = make_float4(0,0,0,0);

    int aRow = lane & 15;
    int aSel = (lane >> 4) * 4;
    int bRow = ((lane >> 4) << 3) | (lane & 7);
    int bSel = ((lane >> 3) & 1) * 4;

    int caRow = tid >> 1, caHalf = tid & 1;          // A: 2 thr/row, 16 words each
    int cbRow = tid >> 2, cbSeg = tid & 3;           // B: 4 thr/row, 8 words each
    size_t aSrc = ((size_t)b * NTOKP + p0 + caRow) * 128 + caHalf * 16;
    size_t bSrc = (size_t)(n0 + cbRow) * 128 + cbSeg * 8;

    auto copy_slab = [&](int slab, int buf) {
        unsigned sb = smb + buf * STG_Q * 4;
        unsigned dA = sb + (caRow*36 + caHalf*16) * 4;
        const unsigned* sh = g_xh + aSrc + slab*32;
        cpa16(dA,      sh);
        cpa16(dA + 16, sh + 4);
        cpa16(dA + 32, sh + 8);
        cpa16(dA + 48, sh + 12);
        unsigned dB = sb + (4608 + cbRow*36 + cbSeg*8) * 4;
        const unsigned* bh_ = g_wqh + bSrc + slab*32;
        const unsigned* bl_ = g_wql + bSrc + slab*32;
        cpa16(dB,            bh_);
        cpa16(dB + 16,       bh_ + 4);
        cpa16(dB + 2304*4,      bl_);
        cpa16(dB + 2304*4 + 16, bl_ + 4);
    };

    copy_slab(0, 0);
    CP_COMMIT();
    int buf = 0;
    for (int s = 0; s < 4; s++) {
        CP_WAIT0();
        __syncthreads();
        if (s < 3) { copy_slab(s + 1, buf ^ 1); CP_COMMIT(); }

        unsigned AhB = smb + buf * STG_Q * 4;
        unsigned BhB = AhB + 4608 * 4;
        unsigned BlB = AhB + 6912 * 4;
        #pragma unroll
        for (int ktl = 0; ktl < 4; ktl++) {
            unsigned ah[2][4];
            #pragma unroll
            for (int mt = 0; mt < 2; mt++) {
                unsigned off = ((wm*32 + mt*16 + aRow) * 36 + ktl*8 + aSel) * 4u;
                ldsm4(ah[mt], AhB + off);
            }
            unsigned bhf[4][2], blf[4][2];
            #pragma unroll
            for (int ntp = 0; ntp < 2; ntp++) {
                unsigned off = ((wn*32 + ntp*16 + bRow) * 36 + ktl*8 + bSel) * 4u;
                unsigned t4[4];
                ldsm4(t4, BhB + off);
                bhf[2*ntp][0] = t4[0]; bhf[2*ntp][1] = t4[1];
                bhf[2*ntp+1][0] = t4[2]; bhf[2*ntp+1][1] = t4[3];
                ldsm4(t4, BlB + off);
                blf[2*ntp][0] = t4[0]; blf[2*ntp][1] = t4[1];
                blf[2*ntp+1][0] = t4[2]; blf[2*ntp+1][1] = t4[3];
            }
            #pragma unroll
            for (int nt = 0; nt < 4; nt++)
                #pragma unroll
                for (int mt = 0; mt < 2; mt++) {
                    mma16(acc[mt][nt], ah[mt], bhf[nt][0], bhf[nt][1]);
                    mma16(acc[mt][nt], ah[mt], blf[nt][0], blf[nt][1]);
                }
        }
        buf ^= 1;
    }

    // epilogue: Q split fp16, K single fp16, V fp32
    #pragma unroll
    for (int nt = 0; nt < 4; nt++) {
        int ng0 = n0 + wn * 32 + nt * 8 + 2 * c;
        int which = ng0 >> 8;
        int h = (ng0 >> 5) & 7;
        int e = ng0 & 31;
        int bhI = b * HEADS + h;
        #pragma unroll
        for (int mt = 0; mt < 2; mt++) {
            int p = p0 + wm * 32 + mt * 16 + r;
            float4 a = acc[mt][nt];
            if (which == 2) {
                if (p < NTOK)
                    *(float2*)&g_v[((size_t)bhI*NTOK + p)*DH + e] = make_float2(a.x, a.y);
                if (p + 8 < NTOK)
                    *(float2*)&g_v[((size_t)bhI*NTOK + p + 8)*DH + e] = make_float2(a.z, a.w);
            } else if (which == 0) {
                const float s = 0.17677669529663687f;
                size_t base = (size_t)bhI * NTOKP * 16 + (e >> 1);
                if (p < NTOK) {
                    unsigned hw, lw; splith2(a.x*s, a.y*s, hw, lw);
                    g_qh[base + (size_t)p*16] = hw; g_ql[base + (size_t)p*16] = lw;
                }
                if (p + 8 < NTOK) {
                    unsigned hw, lw; splith2(a.z*s, a.w*s, hw, lw);
                    g_qh[base + (size_t)(p+8)*16] = hw; g_ql[base + (size_t)(p+8)*16] = lw;
                }
            } else {
                size_t base = (size_t)bhI * NTOKP * 16 + (e >> 1);
                if (p < NTOK)
                    g_kh[base + (size_t)p*16] = packhf(a.x, a.y);
                if (p + 8 < NTOK)
                    g_kh[base + (size_t)(p+8)*16] = packhf(a.z, a.w);
            }
        }
    }
}

// ============================================================
// Kernel 2: flash attention. Two 64-j tiles per barrier window
// (5 windows). DYNAMIC smem (57344 B > 48KB static limit):
//   Kh[buf][sub] 4x1280w @0 | Vh 4x1152w @5120 | Vl @9728.
// ============================================================
#define ATT_KH_W   1280            // 64*20
#define ATT_V_W    1152            // 32*36
#define ATT_VH_OFF 5120            // 4*1280
#define ATT_VL_OFF 9728            // 5120 + 4*1152
#define ATT_SMEM   ((9728 + 4*ATT_V_W) * 4)   // 57344 B

__global__ __launch_bounds__(256, 2) void attn_mma() {
    extern __shared__ __align__(16) unsigned asm_[];
    unsigned smb = sptr(asm_);

    int tid = threadIdx.x;
    int wid = tid >> 5, lane = tid & 31;
    int r = lane >> 2, c = lane & 3;

    int q0 = blockIdx.x * 128;
    int bh = blockIdx.y;
    int h = bh & 7;

    int bRow = ((lane >> 4) << 3) | (lane & 7);
    int bSel = ((lane >> 3) & 1) * 4;

    int ckRow = tid >> 2, ckSeg = tid & 3;
    int cvRow = tid >> 3, cvSeg = tid & 7;
    size_t kSrc = ((size_t)bh * NTOKP + ckRow) * 16 + ckSeg * 4;
    size_t vSrc = ((size_t)bh * 32 + cvRow) * 320 + cvSeg * 4;

    // copy a window = two 64-j tiles (jt = 2*w, 2*w+1)
    auto copy_window = [&](int w, int buf) {
        #pragma unroll
        for (int sub = 0; sub < 2; sub++) {
            int jt = 2*w + sub;
            int slot = buf * 2 + sub;
            cpa16(smb + (slot*ATT_KH_W + ckRow*20 + ckSeg*4) * 4,
                  g_kh + kSrc + (size_t)jt*64*16);
            cpa16(smb + (ATT_VH_OFF + slot*ATT_V_W + cvRow*36 + cvSeg*4) * 4,
                  g_vth + vSrc + jt*32);
            cpa16(smb + (ATT_VL_OFF + slot*ATT_V_W + cvRow*36 + cvSeg*4) * 4,
                  g_vtl + vSrc + jt*32);
        }
    };

    // Q fragments: pre-split fp16 words
    unsigned qh[2][4], ql[2][4];
    {
        const unsigned* qbh = g_qh + (size_t)bh * NTOKP * 16;
        const unsigned* qbl = g_ql + (size_t)bh * NTOKP * 16;
        int pr = q0 + wid * 16 + r;
        #pragma unroll
        for (int kt = 0; kt < 2; kt++) {
            qh[kt][0] = qbh[(size_t)pr*16     + kt*8 + c];
            qh[kt][1] = qbh[(size_t)(pr+8)*16 + kt*8 + c];
            qh[kt][2] = qbh[(size_t)pr*16     + kt*8 + c + 4];
            qh[kt][3] = qbh[(size_t)(pr+8)*16 + kt*8 + c + 4];
            ql[kt][0] = qbl[(size_t)pr*16     + kt*8 + c];
            ql[kt][1] = qbl[(size_t)(pr+8)*16 + kt*8 + c];
            ql[kt][2] = qbl[(size_t)pr*16     + kt*8 + c + 4];
            ql[kt][3] = qbl[(size_t)(pr+8)*16 + kt*8 + c + 4];
        }
    }

    float4 O[4];
    #pragma unroll
    for (int i = 0; i < 4; i++) O[i] = make_float4(0,0,0,0);
    float m0 = -INFINITY, m1 = -INFINITY, l0 = 0.f, l1 = 0.f;

    copy_window(0, 0);
    CP_COMMIT();
    int buf = 0;
    for (int w = 0; w < 5; w++) {
        CP_WAIT0();
        __syncthreads();
        if (w < 4) { copy_window(w + 1, buf ^ 1); CP_COMMIT(); }

        #pragma unroll
        for (int sub = 0; sub < 2; sub++) {
            int j0 = (2*w + sub) * 64;
            int slot = buf * 2 + sub;
            unsigned KhB = smb + slot * ATT_KH_W * 4;
            unsigned VhB = smb + (ATT_VH_OFF + slot * ATT_V_W) * 4;
            unsigned VlB = smb + (ATT_VL_OFF + slot * ATT_V_W) * 4;

            // ---- S = Q K^T ----
            float4 acc[8];
            #pragma unroll
            for (int i = 0; i < 8; i++) acc[i] = make_float4(0,0,0,0);
            #pragma unroll
            for (int kt = 0; kt < 2; kt++) {
                unsigned th[4][4];
                #pragma unroll
                for (int ntp = 0; ntp < 4; ntp++) {
                    unsigned off = ((ntp*16 + bRow) * 20 + kt*8 + bSel) * 4u;
                    ldsm4(th[ntp], KhB + off);
                }
                #pragma unroll
                for (int ntp = 0; ntp < 4; ntp++) {
                    mma16(acc[2*ntp  ], qh[kt], th[ntp][0], th[ntp][1]);
                    mma16(acc[2*ntp+1], qh[kt], th[ntp][2], th[ntp][3]);
                    mma16(acc[2*ntp  ], ql[kt], th[ntp][0], th[ntp][1]);
                    mma16(acc[2*ntp+1], ql[kt], th[ntp][2], th[ntp][3]);
                }
            }

            // ---- bias + tail mask ----
            {
                const float* bp = g_bias + ((size_t)(h * NPAD + q0 + wid*16 + r)) * NPAD + j0;
                #pragma unroll
                for (int nt = 0; nt < 8; nt++) {
                    float2 b0v = *(const float2*)&bp[nt*8 + 2*c];
                    float2 b1v = *(const float2*)&bp[8*NPAD + nt*8 + 2*c];
                    acc[nt].x += b0v.x; acc[nt].y += b0v.y;
                    acc[nt].z += b1v.x; acc[nt].w += b1v.y;
                }
                if (j0 + 64 > NTOK) {
                    #pragma unroll
                    for (int nt = 0; nt < 8; nt++) {
                        int jc = j0 + nt*8 + 2*c;
                        if (jc     >= NTOK) { acc[nt].x = -1e30f; acc[nt].z = -1e30f; }
                        if (jc + 1 >= NTOK) { acc[nt].y = -1e30f; acc[nt].w = -1e30f; }
                    }
                }
            }

            // ---- online softmax (quad reduce) ----
            float t0 = -INFINITY, t1 = -INFINITY;
            #pragma unroll
            for (int nt = 0; nt < 8; nt++) {
                t0 = fmaxf(t0, fmaxf(acc[nt].x, acc[nt].y));
                t1 = fmaxf(t1, fmaxf(acc[nt].z, acc[nt].w));
            }
            #pragma unroll
            for (int off = 1; off <= 2; off <<= 1) {
                t0 = fmaxf(t0, __shfl_xor_sync(0xffffffffu, t0, off));
                t1 = fmaxf(t1, __shfl_xor_sync(0xffffffffu, t1, off));
            }
            float mn0 = fmaxf(m0, t0), mn1 = fmaxf(m1, t1);
            float cor0 = __expf(m0 - mn0), cor1 = __expf(m1 - mn1);
            float s0 = 0.f, s1 = 0.f;
            #pragma unroll
            for (int nt = 0; nt < 8; nt++) {
                acc[nt].x = __expf(acc[nt].x - mn0);
                acc[nt].y = __expf(acc[nt].y - mn0);
                acc[nt].z = __expf(acc[nt].z - mn1);
                acc[nt].w = __expf(acc[nt].w - mn1);
                s0 += acc[nt].x + acc[nt].y;
                s1 += acc[nt].z + acc[nt].w;
            }
            #pragma unroll
            for (int off = 1; off <= 2; off <<= 1) {
                s0 += __shfl_xor_sync(0xffffffffu, s0, off);
                s1 += __shfl_xor_sync(0xffffffffu, s1, off);
            }
            l0 = l0 * cor0 + s0;  m0 = mn0;
            l1 = l1 * cor1 + s1;  m1 = mn1;
            #pragma unroll
            for (int i = 0; i < 4; i++) {
                O[i].x *= cor0; O[i].y *= cor0;
                O[i].z *= cor1; O[i].w *= cor1;
            }

            // ---- O += P V ----
            #pragma unroll
            for (int kt = 0; kt < 4; kt++) {
                unsigned ph[4];
                ph[0] = packhf(acc[2*kt  ].x, acc[2*kt  ].y);
                ph[1] = packhf(acc[2*kt  ].z, acc[2*kt  ].w);
                ph[2] = packhf(acc[2*kt+1].x, acc[2*kt+1].y);
                ph[3] = packhf(acc[2*kt+1].z, acc[2*kt+1].w);
                unsigned th[2][4], tl[2][4];
                #pragma unroll
                for (int ntp = 0; ntp < 2; ntp++) {
                    unsigned off = ((ntp*16 + bRow) * 36 + kt*8 + bSel) * 4u;
                    ldsm4(th[ntp], VhB + off);
                    ldsm4(tl[ntp], VlB + off);
                }
                #pragma unroll
                for (int ntp = 0; ntp < 2; ntp++) {
                    mma16(O[2*ntp  ], ph, th[ntp][0], th[ntp][1]);
                    mma16(O[2*ntp+1], ph, th[ntp][2], th[ntp][3]);
                    mma16(O[2*ntp  ], ph, tl[ntp][0], tl[ntp][1]);
                    mma16(O[2*ntp+1], ph, tl[ntp][2], tl[ntp][3]);
                }
            }
        }
        buf ^= 1;
    }

    // epilogue: O split fp16 -> g_oh/g_ol (b, p, [word])
    float inv0 = 1.f / l0, inv1 = 1.f / l1;
    size_t ob = (size_t)(bh >> 3) * NTOKP * 128 + h * 16;
    #pragma unroll
    for (int nt = 0; nt < 4; nt++) {
        int w2 = nt * 4 + c;
        int p = q0 + wid * 16 + r;
        if (p < NTOK) {
            unsigned hw, lw; splith2(O[nt].x * inv0, O[nt].y * inv0, hw, lw);
            g_oh[ob + (size_t)p*128 + w2] = hw;
            g_ol[ob + (size_t)p*128 + w2] = lw;
        }
        if (p + 8 < NTOK) {
            unsigned hw, lw; splith2(O[nt].z * inv1, O[nt].w * inv1, hw, lw);
            g_oh[ob + (size_t)(p+8)*128 + w2] = hw;
            g_ol[ob + (size_t)(p+8)*128 + w2] = lw;
        }
    }
}

// ============================================================
// Kernel 3: output projection. A=O split, B=w_out single.
// (unchanged structure: slab 32, occ 3)
// ============================================================
#define STG_O 6400
#define OUT_SMEM (2*STG_O*4)   // 51200 B

__global__ __launch_bounds__(256, 3) void out_mma(float* __restrict__ out) {
    extern __shared__ __align__(16) unsigned osm[];
    float (*Cs)[69] = (float(*)[69])osm;

    int b  = blockIdx.z;
    int p0 = blockIdx.x * 128;
    int n0 = blockIdx.y * 64;
    int tid = threadIdx.x;
    int wid = tid >> 5, lane = tid & 31;
    int wm = wid & 3, wn = wid >> 2;
    int r = lane >> 2, c = lane & 3;
    unsigned smb = sptr(osm);

    float4 acc[2][4];
    #pragma unroll
    for (int i = 0; i < 2; i++)
        #pragma unroll
        for (int j = 0; j < 4; j++) acc[i][j] = make_float4(0,0,0,0);

    int aRow = lane & 15;
    int aSel = (lane >> 4) * 4;
    int bRow = ((lane >> 4) << 3) | (lane & 7);
    int bSel = ((lane >> 3) & 1) * 4;

    int caRow = tid >> 1, caHalf = tid & 1;
    int cbRow = tid >> 2, cbSeg = tid & 3;
    size_t aSrc = ((size_t)b * NTOKP + p0 + caRow) * 128 + caHalf * 8;
    size_t bSrc = (size_t)(n0 + cbRow) * 128 + cbSeg * 4;

    auto copy_slab = [&](int slab, int buf) {
        unsigned sb = smb + buf * STG_O * 4;
        unsigned dA  = sb + (caRow*20 + caHalf*8) * 4;
        unsigned dAl = dA + 2560 * 4;
        const unsigned* sh = g_oh + aSrc + slab*16;
        const unsigned* sl = g_ol + aSrc + slab*16;
        cpa16(dA,       sh);  cpa16(dA  + 16, sh + 4);
        cpa16(dAl,      sl);  cpa16(dAl + 16, sl + 4);
        unsigned dB = sb + (5120 + cbRow*20 + cbSeg*4) * 4;
        cpa16(dB, g_woh + bSrc + slab*16);
    };

    copy_slab(0, 0);
    CP_COMMIT();
    int buf = 0;
    for (int s = 0; s < 8; s++) {
        CP_WAIT0();
        __syncthreads();
        if (s < 7) { copy_slab(s + 1, buf ^ 1); CP_COMMIT(); }

        unsigned AhB = smb + buf * STG_O * 4;
        unsigned AlB = AhB + 2560 * 4;
        unsigned BhB = AhB + 5120 * 4;
        #pragma unroll
        for (int ktl = 0; ktl < 2; ktl++) {
            unsigned ah[2][4], al[2][4];
            #pragma unroll
            for (int mt = 0; mt < 2; mt++) {
                unsigned off = ((wm*32 + mt*16 + aRow) * 20 + ktl*8 + aSel) * 4u;
                ldsm4(ah[mt], AhB + off);
                ldsm4(al[mt], AlB + off);
            }
            unsigned bhf[4][2];
            #pragma unroll
            for (int ntp = 0; ntp < 2; ntp++) {
                unsigned off = ((wn*32 + ntp*16 + bRow) * 20 + ktl*8 + bSel) * 4u;
                unsigned t4[4];
                ldsm4(t4, BhB + off);
                bhf[2*ntp][0] = t4[0]; bhf[2*ntp][1] = t4[1];
                bhf[2*ntp+1][0] = t4[2]; bhf[2*ntp+1][1] = t4[3];
            }
            #pragma unroll
            for (int nt = 0; nt < 4; nt++)
                #pragma unroll
                for (int mt = 0; mt < 2; mt++) {
                    mma16(acc[mt][nt], ah[mt], bhf[nt][0], bhf[nt][1]);
                    mma16(acc[mt][nt], al[mt], bhf[nt][0], bhf[nt][1]);
                }
        }
        buf ^= 1;
    }

    __syncthreads();   // staging done before Cs reuse

    #pragma unroll
    for (int mt = 0; mt < 2; mt++) {
        int m = wm * 32 + mt * 16 + r;
        #pragma unroll
        for (int nt = 0; nt < 4; nt++) {
            int n = wn * 32 + nt * 8 + 2 * c;
            Cs[m    ][n    ] = acc[mt][nt].x;
            Cs[m    ][n + 1] = acc[mt][nt].y;
            Cs[m + 8][n    ] = acc[mt][nt].z;
            Cs[m + 8][n + 1] = acc[mt][nt].w;
        }
    }
    __syncthreads();

    #pragma unroll
    for (int it = 0; it < 32; it++) {
        int idx = it * 256 + tid;
        int n = idx >> 7;
        int m = idx & 127;
        int p = p0 + m;
        if (p < NTOK)
            out[((size_t)b * DD + n0 + n) * NTOK + p] = Cs[m][n];
    }
}

// ============================================================
extern "C" void kernel_launch(void* const* d_in, const int* in_sizes, int n_in,
                              void* d_out, int out_size) {
    const float* x          = (const float*)d_in[0];
    const float* w_qkv      = (const float*)d_in[1];
    const float* w_out      = (const float*)d_in[2];
    const float* bias_table = (const float*)d_in[3];
    const int*   rel        = (const int*)d_in[4];
    float* out = (float*)d_out;

    cudaFuncSetAttribute(qkv_mma, cudaFuncAttributeMaxDynamicSharedMemorySize,
                         QKV_SMEM);
    cudaFuncSetAttribute(attn_mma, cudaFuncAttributeMaxDynamicSharedMemorySize,
                         ATT_SMEM);
    cudaFuncSetAttribute(out_mma, cudaFuncAttributeMaxDynamicSharedMemorySize,
                         OUT_SMEM);

    bias_fill<<<(HEADS * NTOK * NTOK + 255) / 256, 256>>>(bias_table, rel);
    prep_w<<<512, 256>>>(w_qkv, w_out);
    prep_x<<<dim3(10, 4, BB), 256>>>(x);
    qkv_mma<<<dim3(5, 12, BB), 256, QKV_SMEM>>>();
    prep_vt<<<dim3(10, NBH), 256>>>();
    attn_mma<<<dim3(5, NBH), 256, ATT_SMEM>>>();
    out_mma<<<dim3(5, 4, BB), 256, OUT_SMEM>>>(out);
}

// round 15
// speedup vs baseline: 1.0823x; 1.0714x over previous
#include <cuda_runtime.h>
#include <cuda_fp16.h>
#include <math.h>

#define BB    64
#define DD    256
#define HEADS 8
#define DH    32
#define NTOK  625
#define NTOKP 640
#define NPAD  640
#define NBH   (BB*HEADS)

// ---- scratch (device globals, zero-initialized) ----
__device__ __align__(128) unsigned g_xh[(size_t)BB*NTOKP*128];   // x single fp16 words
__device__ __align__(128) unsigned g_wqh[768*128];               // w_qkv hi
__device__ __align__(128) unsigned g_wql[768*128];               // w_qkv lo
__device__ __align__(128) unsigned g_woh[256*128];               // w_out single
__device__ __align__(128) unsigned g_qh[(size_t)NBH*NTOKP*16];   // Q hi
__device__ __align__(128) unsigned g_ql[(size_t)NBH*NTOKP*16];   // Q lo
__device__ __align__(128) unsigned g_kh[(size_t)NBH*NTOKP*16];   // K single
__device__ __align__(128) unsigned g_vth[(size_t)NBH*32*320];    // V^T hi
__device__ __align__(128) unsigned g_vtl[(size_t)NBH*32*320];    // V^T lo
__device__ __align__(128) unsigned g_oh[(size_t)BB*NTOKP*128];   // O hi
__device__ __align__(128) unsigned g_ol[(size_t)BB*NTOKP*128];   // O lo
__device__ __align__(16)  float    g_bias[HEADS*NPAD*NPAD];

// ================= fp16 pack/split helpers =================
__device__ __forceinline__ unsigned packhf(float x0, float x1) {
    unsigned u;
    asm("cvt.rn.f16x2.f32 %0, %1, %2;" : "=r"(u) : "f"(x1), "f"(x0));
    return u;
}
__device__ __forceinline__ void splith2(float x0, float x1,
                                        unsigned &h, unsigned &l) {
    h = packhf(x0, x1);
    __half2 hh = *reinterpret_cast<__half2*>(&h);
    l = packhf(x0 - __low2float(hh), x1 - __high2float(hh));
}
__device__ __forceinline__ void mma16(float4 &d, const unsigned a[4],
                                      unsigned b0, unsigned b1) {
    asm volatile(
        "mma.sync.aligned.m16n8k16.row.col.f32.f16.f16.f32 "
        "{%0,%1,%2,%3}, {%4,%5,%6,%7}, {%8,%9}, {%0,%1,%2,%3};"
        : "+f"(d.x), "+f"(d.y), "+f"(d.z), "+f"(d.w)
        : "r"(a[0]), "r"(a[1]), "r"(a[2]), "r"(a[3]), "r"(b0), "r"(b1));
}
// ================= ldmatrix / cp.async helpers =================
__device__ __forceinline__ unsigned sptr(const void* p) {
    return (unsigned)__cvta_generic_to_shared(p);
}
__device__ __forceinline__ void ldsm4(unsigned r[4], unsigned addr) {
    asm volatile("ldmatrix.sync.aligned.m8n8.x4.shared.b16 {%0,%1,%2,%3}, [%4];"
        : "=r"(r[0]), "=r"(r[1]), "=r"(r[2]), "=r"(r[3]) : "r"(addr));
}
__device__ __forceinline__ void cpa16(unsigned dst, const void* src) {
    asm volatile("cp.async.cg.shared.global [%0], [%1], 16;" :: "r"(dst), "l"(src));
}
#define CP_COMMIT() asm volatile("cp.async.commit_group;")
#define CP_WAIT0()  asm volatile("cp.async.wait_group 0;")

// ============================================================
// Kernel 0: prep_all — fused bias_fill + prep_w + prep_x.
// Block ranges: [0,2560) prep_x, [2560,3072) prep_w, rest bias.
// ============================================================
#define PREPX_BLKS 2560
#define PREPW_BLKS 512
#define BIAS_BLKS  12208
#define PREP_GRID  (PREPX_BLKS + PREPW_BLKS + BIAS_BLKS)

__global__ __launch_bounds__(256) void prep_all(const float* __restrict__ x,
                                                const float* __restrict__ wq,
                                                const float* __restrict__ wo,
                                                const float* __restrict__ table,
                                                const int*   __restrict__ rel) {
    __shared__ float sm[64][65];
    int bx = blockIdx.x;
    int t = threadIdx.x;

    if (bx < PREPX_BLKS) {
        // ---- prep_x: transpose x (b,k,p) -> fp16 words (b,p,[k2]) ----
        int id = bx;
        int px = id % 10; id /= 10;
        int ky = id & 3;  int b = id >> 2;
        int p0 = px * 64, k0 = ky * 64;
        int pp = t & 63, kk0 = t >> 6;
        const float* xb = x + ((size_t)b * DD + k0) * NTOK + p0;
        bool pok = (p0 + pp) < NTOK;
        #pragma unroll
        for (int i = 0; i < 16; i++) {
            int kk = kk0 + i * 4;
            sm[kk][pp] = pok ? xb[(size_t)kk * NTOK + pp] : 0.f;
        }
        __syncthreads();
        int row = t >> 2, wseg = t & 3;
        unsigned hw[8];
        #pragma unroll
        for (int i = 0; i < 8; i++) {
            int j2 = wseg * 8 + i;
            hw[i] = packhf(sm[2*j2][row], sm[2*j2+1][row]);
        }
        size_t base = ((size_t)b * NTOKP + p0 + row) * 128 + k0/2 + wseg*8;
        *(uint4*)&g_xh[base]     = *(uint4*)&hw[0];
        *(uint4*)&g_xh[base + 4] = *(uint4*)&hw[4];
    } else if (bx < PREPX_BLKS + PREPW_BLKS) {
        // ---- prep_w ----
        int idx = (bx - PREPX_BLKS) * 256 + t;
        if (idx < 768 * 128) {
            int k2 = idx / 768, n = idx - k2 * 768;
            splith2(wq[(size_t)(2*k2) * 768 + n], wq[(size_t)(2*k2+1) * 768 + n],
                    g_wqh[n*128 + k2], g_wql[n*128 + k2]);
        } else {
            int j = idx - 768 * 128;
            if (j < 256 * 128) {
                int k2 = j / 256, n = j - k2 * 256;
                g_woh[n*128 + k2] = packhf(wo[(size_t)(2*k2) * 256 + n],
                                           wo[(size_t)(2*k2+1) * 256 + n]);
            }
        }
    } else {
        // ---- bias_fill ----
        int idx = (bx - PREPX_BLKS - PREPW_BLKS) * 256 + t;
        const int total = HEADS * NTOK * NTOK;
        if (idx < total) {
            int h = idx / (NTOK * NTOK);
            int r = idx - h * (NTOK * NTOK);
            int i = r / NTOK;
            int j = r - i * NTOK;
            g_bias[(h * NPAD + i) * NPAD + j] = table[rel[r] * HEADS + h];
        }
    }
}

// ============================================================
// Kernel 1: QKV projection (R11 staging: 8 slabs of 32 k).
// Epilogue: Q split, K single, V written DIRECTLY transposed+split
// via shfl_xor(4) row-pairing (replaces prep_vt).
// ============================================================
#define STG_Q 5120
#define QKV_SMEM (2*STG_Q*4)   // 40960 B

__global__ __launch_bounds__(256, 3) void qkv_mma() {
    extern __shared__ __align__(16) unsigned qsm[];
    int b  = blockIdx.z;
    int p0 = blockIdx.x * 128;
    int n0 = blockIdx.y * 64;
    int tid = threadIdx.x;
    int wid = tid >> 5, lane = tid & 31;
    int wm = wid & 3, wn = wid >> 2;
    int r = lane >> 2, c = lane & 3;
    unsigned smb = sptr(qsm);

    float4 acc[2][4];
    #pragma unroll
    for (int i = 0; i < 2; i++)
        #pragma unroll
        for (int j = 0; j < 4; j++) acc[i][j] = make_float4(0,0,0,0);

    int aRow = lane & 15;
    int aSel = (lane >> 4) * 4;
    int bRow = ((lane >> 4) << 3) | (lane & 7);
    int bSel = ((lane >> 3) & 1) * 4;

    int caRow = tid >> 1, caHalf = tid & 1;
    int cbRow = tid >> 2, cbSeg = tid & 3;
    size_t aSrc = ((size_t)b * NTOKP + p0 + caRow) * 128 + caHalf * 8;
    size_t bSrc = (size_t)(n0 + cbRow) * 128 + cbSeg * 4;

    auto copy_slab = [&](int slab, int buf) {
        unsigned sb = smb + buf * STG_Q * 4;
        unsigned dA = sb + (caRow*20 + caHalf*8) * 4;
        const unsigned* sh = g_xh + aSrc + slab*16;
        cpa16(dA,      sh);
        cpa16(dA + 16, sh + 4);
        unsigned dB = sb + (2560 + cbRow*20 + cbSeg*4) * 4;
        cpa16(dB,          g_wqh + bSrc + slab*16);
        cpa16(dB + 1280*4, g_wql + bSrc + slab*16);
    };

    copy_slab(0, 0);
    CP_COMMIT();
    int buf = 0;
    for (int s = 0; s < 8; s++) {
        CP_WAIT0();
        __syncthreads();
        if (s < 7) { copy_slab(s + 1, buf ^ 1); CP_COMMIT(); }

        unsigned AhB = smb + buf * STG_Q * 4;
        unsigned BhB = AhB + 2560 * 4;
        unsigned BlB = AhB + 3840 * 4;
        #pragma unroll
        for (int ktl = 0; ktl < 2; ktl++) {
            unsigned ah[2][4];
            #pragma unroll
            for (int mt = 0; mt < 2; mt++) {
                unsigned off = ((wm*32 + mt*16 + aRow) * 20 + ktl*8 + aSel) * 4u;
                ldsm4(ah[mt], AhB + off);
            }
            unsigned bhf[4][2], blf[4][2];
            #pragma unroll
            for (int ntp = 0; ntp < 2; ntp++) {
                unsigned off = ((wn*32 + ntp*16 + bRow) * 20 + ktl*8 + bSel) * 4u;
                unsigned t4[4];
                ldsm4(t4, BhB + off);
                bhf[2*ntp][0] = t4[0]; bhf[2*ntp][1] = t4[1];
                bhf[2*ntp+1][0] = t4[2]; bhf[2*ntp+1][1] = t4[3];
                ldsm4(t4, BlB + off);
                blf[2*ntp][0] = t4[0]; blf[2*ntp][1] = t4[1];
                blf[2*ntp+1][0] = t4[2]; blf[2*ntp+1][1] = t4[3];
            }
            #pragma unroll
            for (int nt = 0; nt < 4; nt++)
                #pragma unroll
                for (int mt = 0; mt < 2; mt++) {
                    mma16(acc[mt][nt], ah[mt], bhf[nt][0], bhf[nt][1]);
                    mma16(acc[mt][nt], ah[mt], blf[nt][0], blf[nt][1]);
                }
        }
        buf ^= 1;
    }

    // ---- epilogue ----
    #pragma unroll
    for (int nt = 0; nt < 4; nt++) {
        int ng0 = n0 + wn * 32 + nt * 8 + 2 * c;
        int which = ng0 >> 8;          // warp-uniform (see derivation)
        int h = (ng0 >> 5) & 7;
        int e = ng0 & 31;              // even (= 2c + 8*ntpart)
        int bhI = b * HEADS + h;
        #pragma unroll
        for (int mt = 0; mt < 2; mt++) {
            int p = p0 + wm * 32 + mt * 16 + r;
            float4 a = acc[mt][nt];
            if (which == 2) {
                // V: direct transposed split write.
                // Pair rows (2s,2s+1) via shfl_xor(4) (r-bit0 flip).
                float px_ = __shfl_xor_sync(0xffffffffu, a.x, 4);
                float py_ = __shfl_xor_sync(0xffffffffu, a.y, 4);
                float pz_ = __shfl_xor_sync(0xffffffffu, a.z, 4);
                float pw_ = __shfl_xor_sync(0xffffffffu, a.w, 4);
                int p0w = p0 + wm*32 + mt*16;
                bool evenr = ((r & 1) == 0);
                int s = r >> 1;
                int j2 = (p0w >> 1) + (evenr ? s : (4 + s));
                // e-col word: rows (2j2, 2j2+1) at col e;  e+1 likewise
                float v0e, v1e, v0o, v1o;
                if (evenr) { v0e = a.x; v1e = px_; v0o = a.y; v1o = py_; }
                else       { v0e = pz_; v1e = a.z; v0o = pw_; v1o = a.w; }
                size_t vbase = ((size_t)bhI * 32 + e) * 320;
                unsigned hw, lw;
                splith2(v0e, v1e, hw, lw);
                g_vth[vbase + j2] = hw;  g_vtl[vbase + j2] = lw;
                splith2(v0o, v1o, hw, lw);
                g_vth[vbase + 320 + j2] = hw;  g_vtl[vbase + 320 + j2] = lw;
            } else if (which == 0) {
                const float sc = 0.17677669529663687f;
                size_t base = (size_t)bhI * NTOKP * 16 + (e >> 1);
                if (p < NTOK) {
                    unsigned hw, lw; splith2(a.x*sc, a.y*sc, hw, lw);
                    g_qh[base + (size_t)p*16] = hw; g_ql[base + (size_t)p*16] = lw;
                }
                if (p + 8 < NTOK) {
                    unsigned hw, lw; splith2(a.z*sc, a.w*sc, hw, lw);
                    g_qh[base + (size_t)(p+8)*16] = hw; g_ql[base + (size_t)(p+8)*16] = lw;
                }
            } else {
                size_t base = (size_t)bhI * NTOKP * 16 + (e >> 1);
                if (p < NTOK)
                    g_kh[base + (size_t)p*16] = packhf(a.x, a.y);
                if (p + 8 < NTOK)
                    g_kh[base + (size_t)(p+8)*16] = packhf(a.z, a.w);
            }
        }
    }
}

// ============================================================
// Kernel 2: flash attention (R14: two 64-j tiles per window,
// dynamic smem 57344B).
// ============================================================
#define ATT_KH_W   1280
#define ATT_V_W    1152
#define ATT_VH_OFF 5120
#define ATT_VL_OFF 9728
#define ATT_SMEM   ((9728 + 4*ATT_V_W) * 4)   // 57344 B

__global__ __launch_bounds__(256, 2) void attn_mma() {
    extern __shared__ __align__(16) unsigned asm_[];
    unsigned smb = sptr(asm_);

    int tid = threadIdx.x;
    int wid = tid >> 5, lane = tid & 31;
    int r = lane >> 2, c = lane & 3;

    int q0 = blockIdx.x * 128;
    int bh = blockIdx.y;
    int h = bh & 7;

    int bRow = ((lane >> 4) << 3) | (lane & 7);
    int bSel = ((lane >> 3) & 1) * 4;

    int ckRow = tid >> 2, ckSeg = tid & 3;
    int cvRow = tid >> 3, cvSeg = tid & 7;
    size_t kSrc = ((size_t)bh * NTOKP + ckRow) * 16 + ckSeg * 4;
    size_t vSrc = ((size_t)bh * 32 + cvRow) * 320 + cvSeg * 4;

    auto copy_window = [&](int w, int buf) {
        #pragma unroll
        for (int sub = 0; sub < 2; sub++) {
            int jt = 2*w + sub;
            int slot = buf * 2 + sub;
            cpa16(smb + (slot*ATT_KH_W + ckRow*20 + ckSeg*4) * 4,
                  g_kh + kSrc + (size_t)jt*64*16);
            cpa16(smb + (ATT_VH_OFF + slot*ATT_V_W + cvRow*36 + cvSeg*4) * 4,
                  g_vth + vSrc + jt*32);
            cpa16(smb + (ATT_VL_OFF + slot*ATT_V_W + cvRow*36 + cvSeg*4) * 4,
                  g_vtl + vSrc + jt*32);
        }
    };

    unsigned qh[2][4], ql[2][4];
    {
        const unsigned* qbh = g_qh + (size_t)bh * NTOKP * 16;
        const unsigned* qbl = g_ql + (size_t)bh * NTOKP * 16;
        int pr = q0 + wid * 16 + r;
        #pragma unroll
        for (int kt = 0; kt < 2; kt++) {
            qh[kt][0] = qbh[(size_t)pr*16     + kt*8 + c];
            qh[kt][1] = qbh[(size_t)(pr+8)*16 + kt*8 + c];
            qh[kt][2] = qbh[(size_t)pr*16     + kt*8 + c + 4];
            qh[kt][3] = qbh[(size_t)(pr+8)*16 + kt*8 + c + 4];
            ql[kt][0] = qbl[(size_t)pr*16     + kt*8 + c];
            ql[kt][1] = qbl[(size_t)(pr+8)*16 + kt*8 + c];
            ql[kt][2] = qbl[(size_t)pr*16     + kt*8 + c + 4];
            ql[kt][3] = qbl[(size_t)(pr+8)*16 + kt*8 + c + 4];
        }
    }

    float4 O[4];
    #pragma unroll
    for (int i = 0; i < 4; i++) O[i] = make_float4(0,0,0,0);
    float m0 = -INFINITY, m1 = -INFINITY, l0 = 0.f, l1 = 0.f;

    copy_window(0, 0);
    CP_COMMIT();
    int buf = 0;
    for (int w = 0; w < 5; w++) {
        CP_WAIT0();
        __syncthreads();
        if (w < 4) { copy_window(w + 1, buf ^ 1); CP_COMMIT(); }

        #pragma unroll
        for (int sub = 0; sub < 2; sub++) {
            int j0 = (2*w + sub) * 64;
            int slot = buf * 2 + sub;
            unsigned KhB = smb + slot * ATT_KH_W * 4;
            unsigned VhB = smb + (ATT_VH_OFF + slot * ATT_V_W) * 4;
            unsigned VlB = smb + (ATT_VL_OFF + slot * ATT_V_W) * 4;

            float4 acc[8];
            #pragma unroll
            for (int i = 0; i < 8; i++) acc[i] = make_float4(0,0,0,0);
            #pragma unroll
            for (int kt = 0; kt < 2; kt++) {
                unsigned th[4][4];
                #pragma unroll
                for (int ntp = 0; ntp < 4; ntp++) {
                    unsigned off = ((ntp*16 + bRow) * 20 + kt*8 + bSel) * 4u;
                    ldsm4(th[ntp], KhB + off);
                }
                #pragma unroll
                for (int ntp = 0; ntp < 4; ntp++) {
                    mma16(acc[2*ntp  ], qh[kt], th[ntp][0], th[ntp][1]);
                    mma16(acc[2*ntp+1], qh[kt], th[ntp][2], th[ntp][3]);
                    mma16(acc[2*ntp  ], ql[kt], th[ntp][0], th[ntp][1]);
                    mma16(acc[2*ntp+1], ql[kt], th[ntp][2], th[ntp][3]);
                }
            }

            {
                const float* bp = g_bias + ((size_t)(h * NPAD + q0 + wid*16 + r)) * NPAD + j0;
                #pragma unroll
                for (int nt = 0; nt < 8; nt++) {
                    float2 b0v = *(const float2*)&bp[nt*8 + 2*c];
                    float2 b1v = *(const float2*)&bp[8*NPAD + nt*8 + 2*c];
                    acc[nt].x += b0v.x; acc[nt].y += b0v.y;
                    acc[nt].z += b1v.x; acc[nt].w += b1v.y;
                }
                if (j0 + 64 > NTOK) {
                    #pragma unroll
                    for (int nt = 0; nt < 8; nt++) {
                        int jc = j0 + nt*8 + 2*c;
                        if (jc     >= NTOK) { acc[nt].x = -1e30f; acc[nt].z = -1e30f; }
                        if (jc + 1 >= NTOK) { acc[nt].y = -1e30f; acc[nt].w = -1e30f; }
                    }
                }
            }

            float t0 = -INFINITY, t1 = -INFINITY;
            #pragma unroll
            for (int nt = 0; nt < 8; nt++) {
                t0 = fmaxf(t0, fmaxf(acc[nt].x, acc[nt].y));
                t1 = fmaxf(t1, fmaxf(acc[nt].z, acc[nt].w));
            }
            #pragma unroll
            for (int off = 1; off <= 2; off <<= 1) {
                t0 = fmaxf(t0, __shfl_xor_sync(0xffffffffu, t0, off));
                t1 = fmaxf(t1, __shfl_xor_sync(0xffffffffu, t1, off));
            }
            float mn0 = fmaxf(m0, t0), mn1 = fmaxf(m1, t1);
            float cor0 = __expf(m0 - mn0), cor1 = __expf(m1 - mn1);
            float s0 = 0.f, s1 = 0.f;
            #pragma unroll
            for (int nt = 0; nt < 8; nt++) {
                acc[nt].x = __expf(acc[nt].x - mn0);
                acc[nt].y = __expf(acc[nt].y - mn0);
                acc[nt].z = __expf(acc[nt].z - mn1);
                acc[nt].w = __expf(acc[nt].w - mn1);
                s0 += acc[nt].x + acc[nt].y;
                s1 += acc[nt].z + acc[nt].w;
            }
            #pragma unroll
            for (int off = 1; off <= 2; off <<= 1) {
                s0 += __shfl_xor_sync(0xffffffffu, s0, off);
                s1 += __shfl_xor_sync(0xffffffffu, s1, off);
            }
            l0 = l0 * cor0 + s0;  m0 = mn0;
            l1 = l1 * cor1 + s1;  m1 = mn1;
            #pragma unroll
            for (int i = 0; i < 4; i++) {
                O[i].x *= cor0; O[i].y *= cor0;
                O[i].z *= cor1; O[i].w *= cor1;
            }

            #pragma unroll
            for (int kt = 0; kt < 4; kt++) {
                unsigned ph[4];
                ph[0] = packhf(acc[2*kt  ].x, acc[2*kt  ].y);
                ph[1] = packhf(acc[2*kt  ].z, acc[2*kt  ].w);
                ph[2] = packhf(acc[2*kt+1].x, acc[2*kt+1].y);
                ph[3] = packhf(acc[2*kt+1].z, acc[2*kt+1].w);
                unsigned th[2][4], tl[2][4];
                #pragma unroll
                for (int ntp = 0; ntp < 2; ntp++) {
                    unsigned off = ((ntp*16 + bRow) * 36 + kt*8 + bSel) * 4u;
                    ldsm4(th[ntp], VhB + off);
                    ldsm4(tl[ntp], VlB + off);
                }
                #pragma unroll
                for (int ntp = 0; ntp < 2; ntp++) {
                    mma16(O[2*ntp  ], ph, th[ntp][0], th[ntp][1]);
                    mma16(O[2*ntp+1], ph, th[ntp][2], th[ntp][3]);
                    mma16(O[2*ntp  ], ph, tl[ntp][0], tl[ntp][1]);
                    mma16(O[2*ntp+1], ph, tl[ntp][2], tl[ntp][3]);
                }
            }
        }
        buf ^= 1;
    }

    float inv0 = 1.f / l0, inv1 = 1.f / l1;
    size_t ob = (size_t)(bh >> 3) * NTOKP * 128 + h * 16;
    #pragma unroll
    for (int nt = 0; nt < 4; nt++) {
        int w2 = nt * 4 + c;
        int p = q0 + wid * 16 + r;
        if (p < NTOK) {
            unsigned hw, lw; splith2(O[nt].x * inv0, O[nt].y * inv0, hw, lw);
            g_oh[ob + (size_t)p*128 + w2] = hw;
            g_ol[ob + (size_t)p*128 + w2] = lw;
        }
        if (p + 8 < NTOK) {
            unsigned hw, lw; splith2(O[nt].z * inv1, O[nt].w * inv1, hw, lw);
            g_oh[ob + (size_t)(p+8)*128 + w2] = hw;
            g_ol[ob + (size_t)(p+8)*128 + w2] = lw;
        }
    }
}

// ============================================================
// Kernel 3: output projection (unchanged).
// ============================================================
#define STG_O 6400
#define OUT_SMEM (2*STG_O*4)

__global__ __launch_bounds__(256, 3) void out_mma(float* __restrict__ out) {
    extern __shared__ __align__(16) unsigned osm[];
    float (*Cs)[69] = (float(*)[69])osm;

    int b  = blockIdx.z;
    int p0 = blockIdx.x * 128;
    int n0 = blockIdx.y * 64;
    int tid = threadIdx.x;
    int wid = tid >> 5, lane = tid & 31;
    int wm = wid & 3, wn = wid >> 2;
    int r = lane >> 2, c = lane & 3;
    unsigned smb = sptr(osm);

    float4 acc[2][4];
    #pragma unroll
    for (int i = 0; i < 2; i++)
        #pragma unroll
        for (int j = 0; j < 4; j++) acc[i][j] = make_float4(0,0,0,0);

    int aRow = lane & 15;
    int aSel = (lane >> 4) * 4;
    int bRow = ((lane >> 4) << 3) | (lane & 7);
    int bSel = ((lane >> 3) & 1) * 4;

    int caRow = tid >> 1, caHalf = tid & 1;
    int cbRow = tid >> 2, cbSeg = tid & 3;
    size_t aSrc = ((size_t)b * NTOKP + p0 + caRow) * 128 + caHalf * 8;
    size_t bSrc = (size_t)(n0 + cbRow) * 128 + cbSeg * 4;

    auto copy_slab = [&](int slab, int buf) {
        unsigned sb = smb + buf * STG_O * 4;
        unsigned dA  = sb + (caRow*20 + caHalf*8) * 4;
        unsigned dAl = dA + 2560 * 4;
        const unsigned* sh = g_oh + aSrc + slab*16;
        const unsigned* sl = g_ol + aSrc + slab*16;
        cpa16(dA,       sh);  cpa16(dA  + 16, sh + 4);
        cpa16(dAl,      sl);  cpa16(dAl + 16, sl + 4);
        unsigned dB = sb + (5120 + cbRow*20 + cbSeg*4) * 4;
        cpa16(dB, g_woh + bSrc + slab*16);
    };

    copy_slab(0, 0);
    CP_COMMIT();
    int buf = 0;
    for (int s = 0; s < 8; s++) {
        CP_WAIT0();
        __syncthreads();
        if (s < 7) { copy_slab(s + 1, buf ^ 1); CP_COMMIT(); }

        unsigned AhB = smb + buf * STG_O * 4;
        unsigned AlB = AhB + 2560 * 4;
        unsigned BhB = AhB + 5120 * 4;
        #pragma unroll
        for (int ktl = 0; ktl < 2; ktl++) {
            unsigned ah[2][4], al[2][4];
            #pragma unroll
            for (int mt = 0; mt < 2; mt++) {
                unsigned off = ((wm*32 + mt*16 + aRow) * 20 + ktl*8 + aSel) * 4u;
                ldsm4(ah[mt], AhB + off);
                ldsm4(al[mt], AlB + off);
            }
            unsigned bhf[4][2];
            #pragma unroll
            for (int ntp = 0; ntp < 2; ntp++) {
                unsigned off = ((wn*32 + ntp*16 + bRow) * 20 + ktl*8 + bSel) * 4u;
                unsigned t4[4];
                ldsm4(t4, BhB + off);
                bhf[2*ntp][0] = t4[0]; bhf[2*ntp][1] = t4[1];
                bhf[2*ntp+1][0] = t4[2]; bhf[2*ntp+1][1] = t4[3];
            }
            #pragma unroll
            for (int nt = 0; nt < 4; nt++)
                #pragma unroll
                for (int mt = 0; mt < 2; mt++) {
                    mma16(acc[mt][nt], ah[mt], bhf[nt][0], bhf[nt][1]);
                    mma16(acc[mt][nt], al[mt], bhf[nt][0], bhf[nt][1]);
                }
        }
        buf ^= 1;
    }

    __syncthreads();

    #pragma unroll
    for (int mt = 0; mt < 2; mt++) {
        int m = wm * 32 + mt * 16 + r;
        #pragma unroll
        for (int nt = 0; nt < 4; nt++) {
            int n = wn * 32 + nt * 8 + 2 * c;
            Cs[m    ][n    ] = acc[mt][nt].x;
            Cs[m    ][n + 1] = acc[mt][nt].y;
            Cs[m + 8][n    ] = acc[mt][nt].z;
            Cs[m + 8][n + 1] = acc[mt][nt].w;
        }
    }
    __syncthreads();

    #pragma unroll
    for (int it = 0; it < 32; it++) {
        int idx = it * 256 + tid;
        int n = idx >> 7;
        int m = idx & 127;
        int p = p0 + m;
        if (p < NTOK)
            out[((size_t)b * DD + n0 + n) * NTOK + p] = Cs[m][n];
    }
}

// ============================================================
extern "C" void kernel_launch(void* const* d_in, const int* in_sizes, int n_in,
                              void* d_out, int out_size) {
    const float* x          = (const float*)d_in[0];
    const float* w_qkv      = (const float*)d_in[1];
    const float* w_out      = (const float*)d_in[2];
    const float* bias_table = (const float*)d_in[3];
    const int*   rel        = (const int*)d_in[4];
    float* out = (float*)d_out;

    cudaFuncSetAttribute(qkv_mma, cudaFuncAttributeMaxDynamicSharedMemorySize,
                         QKV_SMEM);
    cudaFuncSetAttribute(attn_mma, cudaFuncAttributeMaxDynamicSharedMemorySize,
                         ATT_SMEM);
    cudaFuncSetAttribute(out_mma, cudaFuncAttributeMaxDynamicSharedMemorySize,
                         OUT_SMEM);

    prep_all<<<PREP_GRID, 256>>>(x, w_qkv, w_out, bias_table, rel);
    qkv_mma<<<dim3(5, 12, BB), 256, QKV_SMEM>>>();
    attn_mma<<<dim3(5, NBH), 256, ATT_SMEM>>>();
    out_mma<<<dim3(5, 4, BB), 256, OUT_SMEM>>>(out);
}

// round 16
// speedup vs baseline: 1.1597x; 1.0715x over previous
#include <cuda_runtime.h>
#include <cuda_fp16.h>
#include <math.h>

#define BB    64
#define DD    256
#define HEADS 8
#define DH    32
#define NTOK  625
#define NTOKP 640
#define NPAD  640
#define NBH   (BB*HEADS)

// ---- scratch (device globals, zero-initialized) ----
__device__ __align__(128) unsigned g_xh[(size_t)BB*NTOKP*128];   // x single fp16 words
__device__ __align__(128) unsigned g_wqh[768*128];               // w_qkv hi
__device__ __align__(128) unsigned g_wql[768*128];               // w_qkv lo
__device__ __align__(128) unsigned g_woh[256*128];               // w_out single
__device__ __align__(128) unsigned g_qh[(size_t)NBH*NTOKP*16];   // Q hi
__device__ __align__(128) unsigned g_ql[(size_t)NBH*NTOKP*16];   // Q lo
__device__ __align__(128) unsigned g_kh[(size_t)NBH*NTOKP*16];   // K single
__device__ __align__(128) unsigned g_vth[(size_t)NBH*32*320];    // V^T single fp16
__device__ __align__(128) unsigned g_oh[(size_t)BB*NTOKP*128];   // O hi
__device__ __align__(128) unsigned g_ol[(size_t)BB*NTOKP*128];   // O lo
__device__ __align__(16)  float    g_bias[HEADS*NPAD*NPAD];

// ================= fp16 pack/split helpers =================
__device__ __forceinline__ unsigned packhf(float x0, float x1) {
    unsigned u;
    asm("cvt.rn.f16x2.f32 %0, %1, %2;" : "=r"(u) : "f"(x1), "f"(x0));
    return u;
}
__device__ __forceinline__ void splith2(float x0, float x1,
                                        unsigned &h, unsigned &l) {
    h = packhf(x0, x1);
    __half2 hh = *reinterpret_cast<__half2*>(&h);
    l = packhf(x0 - __low2float(hh), x1 - __high2float(hh));
}
__device__ __forceinline__ void mma16(float4 &d, const unsigned a[4],
                                      unsigned b0, unsigned b1) {
    asm volatile(
        "mma.sync.aligned.m16n8k16.row.col.f32.f16.f16.f32 "
        "{%0,%1,%2,%3}, {%4,%5,%6,%7}, {%8,%9}, {%0,%1,%2,%3};"
        : "+f"(d.x), "+f"(d.y), "+f"(d.z), "+f"(d.w)
        : "r"(a[0]), "r"(a[1]), "r"(a[2]), "r"(a[3]), "r"(b0), "r"(b1));
}
// ================= ldmatrix / cp.async helpers =================
__device__ __forceinline__ unsigned sptr(const void* p) {
    return (unsigned)__cvta_generic_to_shared(p);
}
__device__ __forceinline__ void ldsm4(unsigned r[4], unsigned addr) {
    asm volatile("ldmatrix.sync.aligned.m8n8.x4.shared.b16 {%0,%1,%2,%3}, [%4];"
        : "=r"(r[0]), "=r"(r[1]), "=r"(r[2]), "=r"(r[3]) : "r"(addr));
}
__device__ __forceinline__ void cpa16(unsigned dst, const void* src) {
    asm volatile("cp.async.cg.shared.global [%0], [%1], 16;" :: "r"(dst), "l"(src));
}
#define CP_COMMIT() asm volatile("cp.async.commit_group;")
#define CP_WAIT0()  asm volatile("cp.async.wait_group 0;")

// ============================================================
// Kernel 0: prep_all — fused bias_fill + prep_w + prep_x.
// ============================================================
#define PREPX_BLKS 2560
#define PREPW_BLKS 512
#define BIAS_BLKS  12208
#define PREP_GRID  (PREPX_BLKS + PREPW_BLKS + BIAS_BLKS)

__global__ __launch_bounds__(256) void prep_all(const float* __restrict__ x,
                                                const float* __restrict__ wq,
                                                const float* __restrict__ wo,
                                                const float* __restrict__ table,
                                                const int*   __restrict__ rel) {
    __shared__ float sm[64][65];
    int bx = blockIdx.x;
    int t = threadIdx.x;

    if (bx < PREPX_BLKS) {
        int id = bx;
        int px = id % 10; id /= 10;
        int ky = id & 3;  int b = id >> 2;
        int p0 = px * 64, k0 = ky * 64;
        int pp = t & 63, kk0 = t >> 6;
        const float* xb = x + ((size_t)b * DD + k0) * NTOK + p0;
        bool pok = (p0 + pp) < NTOK;
        #pragma unroll
        for (int i = 0; i < 16; i++) {
            int kk = kk0 + i * 4;
            sm[kk][pp] = pok ? xb[(size_t)kk * NTOK + pp] : 0.f;
        }
        __syncthreads();
        int row = t >> 2, wseg = t & 3;
        unsigned hw[8];
        #pragma unroll
        for (int i = 0; i < 8; i++) {
            int j2 = wseg * 8 + i;
            hw[i] = packhf(sm[2*j2][row], sm[2*j2+1][row]);
        }
        size_t base = ((size_t)b * NTOKP + p0 + row) * 128 + k0/2 + wseg*8;
        *(uint4*)&g_xh[base]     = *(uint4*)&hw[0];
        *(uint4*)&g_xh[base + 4] = *(uint4*)&hw[4];
    } else if (bx < PREPX_BLKS + PREPW_BLKS) {
        int idx = (bx - PREPX_BLKS) * 256 + t;
        if (idx < 768 * 128) {
            int k2 = idx / 768, n = idx - k2 * 768;
            splith2(wq[(size_t)(2*k2) * 768 + n], wq[(size_t)(2*k2+1) * 768 + n],
                    g_wqh[n*128 + k2], g_wql[n*128 + k2]);
        } else {
            int j = idx - 768 * 128;
            if (j < 256 * 128) {
                int k2 = j / 256, n = j - k2 * 256;
                g_woh[n*128 + k2] = packhf(wo[(size_t)(2*k2) * 256 + n],
                                           wo[(size_t)(2*k2+1) * 256 + n]);
            }
        }
    } else {
        int idx = (bx - PREPX_BLKS - PREPW_BLKS) * 256 + t;
        const int total = HEADS * NTOK * NTOK;
        if (idx < total) {
            int h = idx / (NTOK * NTOK);
            int r = idx - h * (NTOK * NTOK);
            int i = r / NTOK;
            int j = r - i * NTOK;
            g_bias[(h * NPAD + i) * NPAD + j] = table[rel[r] * HEADS + h];
        }
    }
}

// ============================================================
// Kernel 1: QKV projection (8 slabs of 32 k). Epilogue: Q split,
// K single, V direct-transposed SINGLE fp16 via shfl_xor(4).
// ============================================================
#define STG_Q 5120
#define QKV_SMEM (2*STG_Q*4)   // 40960 B

__global__ __launch_bounds__(256, 3) void qkv_mma() {
    extern __shared__ __align__(16) unsigned qsm[];
    int b  = blockIdx.z;
    int p0 = blockIdx.x * 128;
    int n0 = blockIdx.y * 64;
    int tid = threadIdx.x;
    int wid = tid >> 5, lane = tid & 31;
    int wm = wid & 3, wn = wid >> 2;
    int r = lane >> 2, c = lane & 3;
    unsigned smb = sptr(qsm);

    float4 acc[2][4];
    #pragma unroll
    for (int i = 0; i < 2; i++)
        #pragma unroll
        for (int j = 0; j < 4; j++) acc[i][j] = make_float4(0,0,0,0);

    int aRow = lane & 15;
    int aSel = (lane >> 4) * 4;
    int bRow = ((lane >> 4) << 3) | (lane & 7);
    int bSel = ((lane >> 3) & 1) * 4;

    int caRow = tid >> 1, caHalf = tid & 1;
    int cbRow = tid >> 2, cbSeg = tid & 3;
    size_t aSrc = ((size_t)b * NTOKP + p0 + caRow) * 128 + caHalf * 8;
    size_t bSrc = (size_t)(n0 + cbRow) * 128 + cbSeg * 4;

    auto copy_slab = [&](int slab, int buf) {
        unsigned sb = smb + buf * STG_Q * 4;
        unsigned dA = sb + (caRow*20 + caHalf*8) * 4;
        const unsigned* sh = g_xh + aSrc + slab*16;
        cpa16(dA,      sh);
        cpa16(dA + 16, sh + 4);
        unsigned dB = sb + (2560 + cbRow*20 + cbSeg*4) * 4;
        cpa16(dB,          g_wqh + bSrc + slab*16);
        cpa16(dB + 1280*4, g_wql + bSrc + slab*16);
    };

    copy_slab(0, 0);
    CP_COMMIT();
    int buf = 0;
    for (int s = 0; s < 8; s++) {
        CP_WAIT0();
        __syncthreads();
        if (s < 7) { copy_slab(s + 1, buf ^ 1); CP_COMMIT(); }

        unsigned AhB = smb + buf * STG_Q * 4;
        unsigned BhB = AhB + 2560 * 4;
        unsigned BlB = AhB + 3840 * 4;
        #pragma unroll
        for (int ktl = 0; ktl < 2; ktl++) {
            unsigned ah[2][4];
            #pragma unroll
            for (int mt = 0; mt < 2; mt++) {
                unsigned off = ((wm*32 + mt*16 + aRow) * 20 + ktl*8 + aSel) * 4u;
                ldsm4(ah[mt], AhB + off);
            }
            unsigned bhf[4][2], blf[4][2];
            #pragma unroll
            for (int ntp = 0; ntp < 2; ntp++) {
                unsigned off = ((wn*32 + ntp*16 + bRow) * 20 + ktl*8 + bSel) * 4u;
                unsigned t4[4];
                ldsm4(t4, BhB + off);
                bhf[2*ntp][0] = t4[0]; bhf[2*ntp][1] = t4[1];
                bhf[2*ntp+1][0] = t4[2]; bhf[2*ntp+1][1] = t4[3];
                ldsm4(t4, BlB + off);
                blf[2*ntp][0] = t4[0]; blf[2*ntp][1] = t4[1];
                blf[2*ntp+1][0] = t4[2]; blf[2*ntp+1][1] = t4[3];
            }
            #pragma unroll
            for (int nt = 0; nt < 4; nt++)
                #pragma unroll
                for (int mt = 0; mt < 2; mt++) {
                    mma16(acc[mt][nt], ah[mt], bhf[nt][0], bhf[nt][1]);
                    mma16(acc[mt][nt], ah[mt], blf[nt][0], blf[nt][1]);
                }
        }
        buf ^= 1;
    }

    // ---- epilogue ----
    #pragma unroll
    for (int nt = 0; nt < 4; nt++) {
        int ng0 = n0 + wn * 32 + nt * 8 + 2 * c;
        int which = ng0 >> 8;
        int h = (ng0 >> 5) & 7;
        int e = ng0 & 31;
        int bhI = b * HEADS + h;
        #pragma unroll
        for (int mt = 0; mt < 2; mt++) {
            int p = p0 + wm * 32 + mt * 16 + r;
            float4 a = acc[mt][nt];
            if (which == 2) {
                // V: direct transposed SINGLE fp16 write via shfl_xor(4)
                float px_ = __shfl_xor_sync(0xffffffffu, a.x, 4);
                float py_ = __shfl_xor_sync(0xffffffffu, a.y, 4);
                float pz_ = __shfl_xor_sync(0xffffffffu, a.z, 4);
                float pw_ = __shfl_xor_sync(0xffffffffu, a.w, 4);
                int p0w = p0 + wm*32 + mt*16;
                bool evenr = ((r & 1) == 0);
                int s = r >> 1;
                int j2 = (p0w >> 1) + (evenr ? s : (4 + s));
                float v0e, v1e, v0o, v1o;
                if (evenr) { v0e = a.x; v1e = px_; v0o = a.y; v1o = py_; }
                else       { v0e = pz_; v1e = a.z; v0o = pw_; v1o = a.w; }
                size_t vbase = ((size_t)bhI * 32 + e) * 320;
                g_vth[vbase + j2]       = packhf(v0e, v1e);
                g_vth[vbase + 320 + j2] = packhf(v0o, v1o);
            } else if (which == 0) {
                const float sc = 0.17677669529663687f;
                size_t base = (size_t)bhI * NTOKP * 16 + (e >> 1);
                if (p < NTOK) {
                    unsigned hw, lw; splith2(a.x*sc, a.y*sc, hw, lw);
                    g_qh[base + (size_t)p*16] = hw; g_ql[base + (size_t)p*16] = lw;
                }
                if (p + 8 < NTOK) {
                    unsigned hw, lw; splith2(a.z*sc, a.w*sc, hw, lw);
                    g_qh[base + (size_t)(p+8)*16] = hw; g_ql[base + (size_t)(p+8)*16] = lw;
                }
            } else {
                size_t base = (size_t)bhI * NTOKP * 16 + (e >> 1);
                if (p < NTOK)
                    g_kh[base + (size_t)p*16] = packhf(a.x, a.y);
                if (p + 8 < NTOK)
                    g_kh[base + (size_t)(p+8)*16] = packhf(a.z, a.w);
            }
        }
    }
}

// ============================================================
// Kernel 2: flash attention. Two 64-j tiles per window; V single
// fp16 (P·V = 16 mma per subtile, was 32). Smem 38912 B.
// ============================================================
#define ATT_KH_W   1280
#define ATT_V_W    1152
#define ATT_VH_OFF 5120            // 4*1280
#define ATT_SMEM   ((ATT_VH_OFF + 4*ATT_V_W) * 4)   // 38912 B

__global__ __launch_bounds__(256, 2) void attn_mma() {
    extern __shared__ __align__(16) unsigned asm_[];
    unsigned smb = sptr(asm_);

    int tid = threadIdx.x;
    int wid = tid >> 5, lane = tid & 31;
    int r = lane >> 2, c = lane & 3;

    int q0 = blockIdx.x * 128;
    int bh = blockIdx.y;
    int h = bh & 7;

    int bRow = ((lane >> 4) << 3) | (lane & 7);
    int bSel = ((lane >> 3) & 1) * 4;

    int ckRow = tid >> 2, ckSeg = tid & 3;
    int cvRow = tid >> 3, cvSeg = tid & 7;
    size_t kSrc = ((size_t)bh * NTOKP + ckRow) * 16 + ckSeg * 4;
    size_t vSrc = ((size_t)bh * 32 + cvRow) * 320 + cvSeg * 4;

    auto copy_window = [&](int w, int buf) {
        #pragma unroll
        for (int sub = 0; sub < 2; sub++) {
            int jt = 2*w + sub;
            int slot = buf * 2 + sub;
            cpa16(smb + (slot*ATT_KH_W + ckRow*20 + ckSeg*4) * 4,
                  g_kh + kSrc + (size_t)jt*64*16);
            cpa16(smb + (ATT_VH_OFF + slot*ATT_V_W + cvRow*36 + cvSeg*4) * 4,
                  g_vth + vSrc + jt*32);
        }
    };

    unsigned qh[2][4], ql[2][4];
    {
        const unsigned* qbh = g_qh + (size_t)bh * NTOKP * 16;
        const unsigned* qbl = g_ql + (size_t)bh * NTOKP * 16;
        int pr = q0 + wid * 16 + r;
        #pragma unroll
        for (int kt = 0; kt < 2; kt++) {
            qh[kt][0] = qbh[(size_t)pr*16     + kt*8 + c];
            qh[kt][1] = qbh[(size_t)(pr+8)*16 + kt*8 + c];
            qh[kt][2] = qbh[(size_t)pr*16     + kt*8 + c + 4];
            qh[kt][3] = qbh[(size_t)(pr+8)*16 + kt*8 + c + 4];
            ql[kt][0] = qbl[(size_t)pr*16     + kt*8 + c];
            ql[kt][1] = qbl[(size_t)(pr+8)*16 + kt*8 + c];
            ql[kt][2] = qbl[(size_t)pr*16     + kt*8 + c + 4];
            ql[kt][3] = qbl[(size_t)(pr+8)*16 + kt*8 + c + 4];
        }
    }

    float4 O[4];
    #pragma unroll
    for (int i = 0; i < 4; i++) O[i] = make_float4(0,0,0,0);
    float m0 = -INFINITY, m1 = -INFINITY, l0 = 0.f, l1 = 0.f;

    copy_window(0, 0);
    CP_COMMIT();
    int buf = 0;
    for (int w = 0; w < 5; w++) {
        CP_WAIT0();
        __syncthreads();
        if (w < 4) { copy_window(w + 1, buf ^ 1); CP_COMMIT(); }

        #pragma unroll
        for (int sub = 0; sub < 2; sub++) {
            int j0 = (2*w + sub) * 64;
            int slot = buf * 2 + sub;
            unsigned KhB = smb + slot * ATT_KH_W * 4;
            unsigned VhB = smb + (ATT_VH_OFF + slot * ATT_V_W) * 4;

            float4 acc[8];
            #pragma unroll
            for (int i = 0; i < 8; i++) acc[i] = make_float4(0,0,0,0);
            #pragma unroll
            for (int kt = 0; kt < 2; kt++) {
                unsigned th[4][4];
                #pragma unroll
                for (int ntp = 0; ntp < 4; ntp++) {
                    unsigned off = ((ntp*16 + bRow) * 20 + kt*8 + bSel) * 4u;
                    ldsm4(th[ntp], KhB + off);
                }
                #pragma unroll
                for (int ntp = 0; ntp < 4; ntp++) {
                    mma16(acc[2*ntp  ], qh[kt], th[ntp][0], th[ntp][1]);
                    mma16(acc[2*ntp+1], qh[kt], th[ntp][2], th[ntp][3]);
                    mma16(acc[2*ntp  ], ql[kt], th[ntp][0], th[ntp][1]);
                    mma16(acc[2*ntp+1], ql[kt], th[ntp][2], th[ntp][3]);
                }
            }

            {
                const float* bp = g_bias + ((size_t)(h * NPAD + q0 + wid*16 + r)) * NPAD + j0;
                #pragma unroll
                for (int nt = 0; nt < 8; nt++) {
                    float2 b0v = *(const float2*)&bp[nt*8 + 2*c];
                    float2 b1v = *(const float2*)&bp[8*NPAD + nt*8 + 2*c];
                    acc[nt].x += b0v.x; acc[nt].y += b0v.y;
                    acc[nt].z += b1v.x; acc[nt].w += b1v.y;
                }
                if (j0 + 64 > NTOK) {
                    #pragma unroll
                    for (int nt = 0; nt < 8; nt++) {
                        int jc = j0 + nt*8 + 2*c;
                        if (jc     >= NTOK) { acc[nt].x = -1e30f; acc[nt].z = -1e30f; }
                        if (jc + 1 >= NTOK) { acc[nt].y = -1e30f; acc[nt].w = -1e30f; }
                    }
                }
            }

            float t0 = -INFINITY, t1 = -INFINITY;
            #pragma unroll
            for (int nt = 0; nt < 8; nt++) {
                t0 = fmaxf(t0, fmaxf(acc[nt].x, acc[nt].y));
                t1 = fmaxf(t1, fmaxf(acc[nt].z, acc[nt].w));
            }
            #pragma unroll
            for (int off = 1; off <= 2; off <<= 1) {
                t0 = fmaxf(t0, __shfl_xor_sync(0xffffffffu, t0, off));
                t1 = fmaxf(t1, __shfl_xor_sync(0xffffffffu, t1, off));
            }
            float mn0 = fmaxf(m0, t0), mn1 = fmaxf(m1, t1);
            float cor0 = __expf(m0 - mn0), cor1 = __expf(m1 - mn1);
            float s0 = 0.f, s1 = 0.f;
            #pragma unroll
            for (int nt = 0; nt < 8; nt++) {
                acc[nt].x = __expf(acc[nt].x - mn0);
                acc[nt].y = __expf(acc[nt].y - mn0);
                acc[nt].z = __expf(acc[nt].z - mn1);
                acc[nt].w = __expf(acc[nt].w - mn1);
                s0 += acc[nt].x + acc[nt].y;
                s1 += acc[nt].z + acc[nt].w;
            }
            #pragma unroll
            for (int off = 1; off <= 2; off <<= 1) {
                s0 += __shfl_xor_sync(0xffffffffu, s0, off);
                s1 += __shfl_xor_sync(0xffffffffu, s1, off);
            }
            l0 = l0 * cor0 + s0;  m0 = mn0;
            l1 = l1 * cor1 + s1;  m1 = mn1;
            #pragma unroll
            for (int i = 0; i < 4; i++) {
                O[i].x *= cor0; O[i].y *= cor0;
                O[i].z *= cor1; O[i].w *= cor1;
            }

            // ---- O += P V (V single fp16) ----
            #pragma unroll
            for (int kt = 0; kt < 4; kt++) {
                unsigned ph[4];
                ph[0] = packhf(acc[2*kt  ].x, acc[2*kt  ].y);
                ph[1] = packhf(acc[2*kt  ].z, acc[2*kt  ].w);
                ph[2] = packhf(acc[2*kt+1].x, acc[2*kt+1].y);
                ph[3] = packhf(acc[2*kt+1].z, acc[2*kt+1].w);
                #pragma unroll
                for (int ntp = 0; ntp < 2; ntp++) {
                    unsigned off = ((ntp*16 + bRow) * 36 + kt*8 + bSel) * 4u;
                    unsigned th[4];
                    ldsm4(th, VhB + off);
                    mma16(O[2*ntp  ], ph, th[0], th[1]);
                    mma16(O[2*ntp+1], ph, th[2], th[3]);
                }
            }
        }
        buf ^= 1;
    }

    float inv0 = 1.f / l0, inv1 = 1.f / l1;
    size_t ob = (size_t)(bh >> 3) * NTOKP * 128 + h * 16;
    #pragma unroll
    for (int nt = 0; nt < 4; nt++) {
        int w2 = nt * 4 + c;
        int p = q0 + wid * 16 + r;
        if (p < NTOK) {
            unsigned hw, lw; splith2(O[nt].x * inv0, O[nt].y * inv0, hw, lw);
            g_oh[ob + (size_t)p*128 + w2] = hw;
            g_ol[ob + (size_t)p*128 + w2] = lw;
        }
        if (p + 8 < NTOK) {
            unsigned hw, lw; splith2(O[nt].z * inv1, O[nt].w * inv1, hw, lw);
            g_oh[ob + (size_t)(p+8)*128 + w2] = hw;
            g_ol[ob + (size_t)(p+8)*128 + w2] = lw;
        }
    }
}

// ============================================================
// Kernel 3: output projection (unchanged).
// ============================================================
#define STG_O 6400
#define OUT_SMEM (2*STG_O*4)

__global__ __launch_bounds__(256, 3) void out_mma(float* __restrict__ out) {
    extern __shared__ __align__(16) unsigned osm[];
    float (*Cs)[69] = (float(*)[69])osm;

    int b  = blockIdx.z;
    int p0 = blockIdx.x * 128;
    int n0 = blockIdx.y * 64;
    int tid = threadIdx.x;
    int wid = tid >> 5, lane = tid & 31;
    int wm = wid & 3, wn = wid >> 2;
    int r = lane >> 2, c = lane & 3;
    unsigned smb = sptr(osm);

    float4 acc[2][4];
    #pragma unroll
    for (int i = 0; i < 2; i++)
        #pragma unroll
        for (int j = 0; j < 4; j++) acc[i][j] = make_float4(0,0,0,0);

    int aRow = lane & 15;
    int aSel = (lane >> 4) * 4;
    int bRow = ((lane >> 4) << 3) | (lane & 7);
    int bSel = ((lane >> 3) & 1) * 4;

    int caRow = tid >> 1, caHalf = tid & 1;
    int cbRow = tid >> 2, cbSeg = tid & 3;
    size_t aSrc = ((size_t)b * NTOKP + p0 + caRow) * 128 + caHalf * 8;
    size_t bSrc = (size_t)(n0 + cbRow) * 128 + cbSeg * 4;

    auto copy_slab = [&](int slab, int buf) {
        unsigned sb = smb + buf * STG_O * 4;
        unsigned dA  = sb + (caRow*20 + caHalf*8) * 4;
        unsigned dAl = dA + 2560 * 4;
        const unsigned* sh = g_oh + aSrc + slab*16;
        const unsigned* sl = g_ol + aSrc + slab*16;
        cpa16(dA,       sh);  cpa16(dA  + 16, sh + 4);
        cpa16(dAl,      sl);  cpa16(dAl + 16, sl + 4);
        unsigned dB = sb + (5120 + cbRow*20 + cbSeg*4) * 4;
        cpa16(dB, g_woh + bSrc + slab*16);
    };

    copy_slab(0, 0);
    CP_COMMIT();
    int buf = 0;
    for (int s = 0; s < 8; s++) {
        CP_WAIT0();
        __syncthreads();
        if (s < 7) { copy_slab(s + 1, buf ^ 1); CP_COMMIT(); }

        unsigned AhB = smb + buf * STG_O * 4;
        unsigned AlB = AhB + 2560 * 4;
        unsigned BhB = AhB + 5120 * 4;
        #pragma unroll
        for (int ktl = 0; ktl < 2; ktl++) {
            unsigned ah[2][4], al[2][4];
            #pragma unroll
            for (int mt = 0; mt < 2; mt++) {
                unsigned off = ((wm*32 + mt*16 + aRow) * 20 + ktl*8 + aSel) * 4u;
                ldsm4(ah[mt], AhB + off);
                ldsm4(al[mt], AlB + off);
            }
            unsigned bhf[4][2];
            #pragma unroll
            for (int ntp = 0; ntp < 2; ntp++) {
                unsigned off = ((wn*32 + ntp*16 + bRow) * 20 + ktl*8 + bSel) * 4u;
                unsigned t4[4];
                ldsm4(t4, BhB + off);
                bhf[2*ntp][0] = t4[0]; bhf[2*ntp][1] = t4[1];
                bhf[2*ntp+1][0] = t4[2]; bhf[2*ntp+1][1] = t4[3];
            }
            #pragma unroll
            for (int nt = 0; nt < 4; nt++)
                #pragma unroll
                for (int mt = 0; mt < 2; mt++) {
                    mma16(acc[mt][nt], ah[mt], bhf[nt][0], bhf[nt][1]);
                    mma16(acc[mt][nt], al[mt], bhf[nt][0], bhf[nt][1]);
                }
        }
        buf ^= 1;
    }

    __syncthreads();

    #pragma unroll
    for (int mt = 0; mt < 2; mt++) {
        int m = wm * 32 + mt * 16 + r;
        #pragma unroll
        for (int nt = 0; nt < 4; nt++) {
            int n = wn * 32 + nt * 8 + 2 * c;
            Cs[m    ][n    ] = acc[mt][nt].x;
            Cs[m    ][n + 1] = acc[mt][nt].y;
            Cs[m + 8][n    ] = acc[mt][nt].z;
            Cs[m + 8][n + 1] = acc[mt][nt].w;
        }
    }
    __syncthreads();

    #pragma unroll
    for (int it = 0; it < 32; it++) {
        int idx = it * 256 + tid;
        int n = idx >> 7;
        int m = idx & 127;
        int p = p0 + m;
        if (p < NTOK)
            out[((size_t)b * DD + n0 + n) * NTOK + p] = Cs[m][n];
    }
}

// ============================================================
extern "C" void kernel_launch(void* const* d_in, const int* in_sizes, int n_in,
                              void* d_out, int out_size) {
    const float* x          = (const float*)d_in[0];
    const float* w_qkv      = (const float*)d_in[1];
    const float* w_out      = (const float*)d_in[2];
    const float* bias_table = (const float*)d_in[3];
    const int*   rel        = (const int*)d_in[4];
    float* out = (float*)d_out;

    cudaFuncSetAttribute(qkv_mma, cudaFuncAttributeMaxDynamicSharedMemorySize,
                         QKV_SMEM);
    cudaFuncSetAttribute(attn_mma, cudaFuncAttributeMaxDynamicSharedMemorySize,
                         ATT_SMEM);
    cudaFuncSetAttribute(out_mma, cudaFuncAttributeMaxDynamicSharedMemorySize,
                         OUT_SMEM);

    prep_all<<<PREP_GRID, 256>>>(x, w_qkv, w_out, bias_table, rel);
    qkv_mma<<<dim3(5, 12, BB), 256, QKV_SMEM>>>();
    attn_mma<<<dim3(5, NBH), 256, ATT_SMEM>>>();
    out_mma<<<dim3(5, 4, BB), 256, OUT_SMEM>>>(out);
}

// round 17
// speedup vs baseline: 1.3276x; 1.1447x over previous
#include <cuda_runtime.h>
#include <cuda_fp16.h>
#include <math.h>

#define BB    64
#define DD    256
#define HEADS 8
#define DH    32
#define NTOK  625
#define NTOKP 640
#define NPAD  640
#define NBH   (BB*HEADS)

// ---- scratch (device globals, zero-initialized) ----
__device__ __align__(128) unsigned g_xh[(size_t)BB*NTOKP*128];   // x single fp16 words
__device__ __align__(128) unsigned g_wqh[768*128];               // w_qkv single fp16
__device__ __align__(128) unsigned g_woh[256*128];               // w_out single fp16
__device__ __align__(128) unsigned g_qh[(size_t)NBH*NTOKP*16];   // Q hi
__device__ __align__(128) unsigned g_ql[(size_t)NBH*NTOKP*16];   // Q lo
__device__ __align__(128) unsigned g_kh[(size_t)NBH*NTOKP*16];   // K single
__device__ __align__(128) unsigned g_vth[(size_t)NBH*32*320];    // V^T single fp16
__device__ __align__(128) unsigned g_oh[(size_t)BB*NTOKP*128];   // O single fp16
__device__ __align__(16)  float    g_bias[HEADS*NPAD*NPAD];

// ================= fp16 pack/split helpers =================
__device__ __forceinline__ unsigned packhf(float x0, float x1) {
    unsigned u;
    asm("cvt.rn.f16x2.f32 %0, %1, %2;" : "=r"(u) : "f"(x1), "f"(x0));
    return u;
}
__device__ __forceinline__ void splith2(float x0, float x1,
                                        unsigned &h, unsigned &l) {
    h = packhf(x0, x1);
    __half2 hh = *reinterpret_cast<__half2*>(&h);
    l = packhf(x0 - __low2float(hh), x1 - __high2float(hh));
}
__device__ __forceinline__ void mma16(float4 &d, const unsigned a[4],
                                      unsigned b0, unsigned b1) {
    asm volatile(
        "mma.sync.aligned.m16n8k16.row.col.f32.f16.f16.f32 "
        "{%0,%1,%2,%3}, {%4,%5,%6,%7}, {%8,%9}, {%0,%1,%2,%3};"
        : "+f"(d.x), "+f"(d.y), "+f"(d.z), "+f"(d.w)
        : "r"(a[0]), "r"(a[1]), "r"(a[2]), "r"(a[3]), "r"(b0), "r"(b1));
}
// ================= ldmatrix / cp.async helpers =================
__device__ __forceinline__ unsigned sptr(const void* p) {
    return (unsigned)__cvta_generic_to_shared(p);
}
__device__ __forceinline__ void ldsm4(unsigned r[4], unsigned addr) {
    asm volatile("ldmatrix.sync.aligned.m8n8.x4.shared.b16 {%0,%1,%2,%3}, [%4];"
        : "=r"(r[0]), "=r"(r[1]), "=r"(r[2]), "=r"(r[3]) : "r"(addr));
}
__device__ __forceinline__ void cpa16(unsigned dst, const void* src) {
    asm volatile("cp.async.cg.shared.global [%0], [%1], 16;" :: "r"(dst), "l"(src));
}
#define CP_COMMIT() asm volatile("cp.async.commit_group;")
#define CP_WAIT0()  asm volatile("cp.async.wait_group 0;")

// ============================================================
// Kernel 0: prep_all — fused bias_fill + prep_w + prep_x.
// ============================================================
#define PREPX_BLKS 2560
#define PREPW_BLKS 512
#define BIAS_BLKS  12208
#define PREP_GRID  (PREPX_BLKS + PREPW_BLKS + BIAS_BLKS)

__global__ __launch_bounds__(256) void prep_all(const float* __restrict__ x,
                                                const float* __restrict__ wq,
                                                const float* __restrict__ wo,
                                                const float* __restrict__ table,
                                                const int*   __restrict__ rel) {
    __shared__ float sm[64][65];
    int bx = blockIdx.x;
    int t = threadIdx.x;

    if (bx < PREPX_BLKS) {
        int id = bx;
        int px = id % 10; id /= 10;
        int ky = id & 3;  int b = id >> 2;
        int p0 = px * 64, k0 = ky * 64;
        int pp = t & 63, kk0 = t >> 6;
        const float* xb = x + ((size_t)b * DD + k0) * NTOK + p0;
        bool pok = (p0 + pp) < NTOK;
        #pragma unroll
        for (int i = 0; i < 16; i++) {
            int kk = kk0 + i * 4;
            sm[kk][pp] = pok ? xb[(size_t)kk * NTOK + pp] : 0.f;
        }
        __syncthreads();
        int row = t >> 2, wseg = t & 3;
        unsigned hw[8];
        #pragma unroll
        for (int i = 0; i < 8; i++) {
            int j2 = wseg * 8 + i;
            hw[i] = packhf(sm[2*j2][row], sm[2*j2+1][row]);
        }
        size_t base = ((size_t)b * NTOKP + p0 + row) * 128 + k0/2 + wseg*8;
        *(uint4*)&g_xh[base]     = *(uint4*)&hw[0];
        *(uint4*)&g_xh[base + 4] = *(uint4*)&hw[4];
    } else if (bx < PREPX_BLKS + PREPW_BLKS) {
        int idx = (bx - PREPX_BLKS) * 256 + t;
        if (idx < 768 * 128) {
            int k2 = idx / 768, n = idx - k2 * 768;
            g_wqh[n*128 + k2] = packhf(wq[(size_t)(2*k2) * 768 + n],
                                       wq[(size_t)(2*k2+1) * 768 + n]);
        } else {
            int j = idx - 768 * 128;
            if (j < 256 * 128) {
                int k2 = j / 256, n = j - k2 * 256;
                g_woh[n*128 + k2] = packhf(wo[(size_t)(2*k2) * 256 + n],
                                           wo[(size_t)(2*k2+1) * 256 + n]);
            }
        }
    } else {
        int idx = (bx - PREPX_BLKS - PREPW_BLKS) * 256 + t;
        const int total = HEADS * NTOK * NTOK;
        if (idx < total) {
            int h = idx / (NTOK * NTOK);
            int r = idx - h * (NTOK * NTOK);
            int i = r / NTOK;
            int j = r - i * NTOK;
            g_bias[(h * NPAD + i) * NPAD + j] = table[rel[r] * HEADS + h];
        }
    }
}

// ============================================================
// Kernel 1: QKV projection — plain fp16 (x single x w single).
// 8 slabs of 32 k; stage: A[128][20] @0 | Bh[64][20] @2560.
// ============================================================
#define STG_Q 3840
#define QKV_SMEM (2*STG_Q*4)   // 30720 B

__global__ __launch_bounds__(256, 3) void qkv_mma() {
    extern __shared__ __align__(16) unsigned qsm[];
    int b  = blockIdx.z;
    int p0 = blockIdx.x * 128;
    int n0 = blockIdx.y * 64;
    int tid = threadIdx.x;
    int wid = tid >> 5, lane = tid & 31;
    int wm = wid & 3, wn = wid >> 2;
    int r = lane >> 2, c = lane & 3;
    unsigned smb = sptr(qsm);

    float4 acc[2][4];
    #pragma unroll
    for (int i = 0; i < 2; i++)
        #pragma unroll
        for (int j = 0; j < 4; j++) acc[i][j] = make_float4(0,0,0,0);

    int aRow = lane & 15;
    int aSel = (lane >> 4) * 4;
    int bRow = ((lane >> 4) << 3) | (lane & 7);
    int bSel = ((lane >> 3) & 1) * 4;

    int caRow = tid >> 1, caHalf = tid & 1;
    int cbRow = tid >> 2, cbSeg = tid & 3;
    size_t aSrc = ((size_t)b * NTOKP + p0 + caRow) * 128 + caHalf * 8;
    size_t bSrc = (size_t)(n0 + cbRow) * 128 + cbSeg * 4;

    auto copy_slab = [&](int slab, int buf) {
        unsigned sb = smb + buf * STG_Q * 4;
        unsigned dA = sb + (caRow*20 + caHalf*8) * 4;
        const unsigned* sh = g_xh + aSrc + slab*16;
        cpa16(dA,      sh);
        cpa16(dA + 16, sh + 4);
        unsigned dB = sb + (2560 + cbRow*20 + cbSeg*4) * 4;
        cpa16(dB, g_wqh + bSrc + slab*16);
    };

    copy_slab(0, 0);
    CP_COMMIT();
    int buf = 0;
    for (int s = 0; s < 8; s++) {
        CP_WAIT0();
        __syncthreads();
        if (s < 7) { copy_slab(s + 1, buf ^ 1); CP_COMMIT(); }

        unsigned AhB = smb + buf * STG_Q * 4;
        unsigned BhB = AhB + 2560 * 4;
        #pragma unroll
        for (int ktl = 0; ktl < 2; ktl++) {
            unsigned ah[2][4];
            #pragma unroll
            for (int mt = 0; mt < 2; mt++) {
                unsigned off = ((wm*32 + mt*16 + aRow) * 20 + ktl*8 + aSel) * 4u;
                ldsm4(ah[mt], AhB + off);
            }
            unsigned bhf[4][2];
            #pragma unroll
            for (int ntp = 0; ntp < 2; ntp++) {
                unsigned off = ((wn*32 + ntp*16 + bRow) * 20 + ktl*8 + bSel) * 4u;
                unsigned t4[4];
                ldsm4(t4, BhB + off);
                bhf[2*ntp][0] = t4[0]; bhf[2*ntp][1] = t4[1];
                bhf[2*ntp+1][0] = t4[2]; bhf[2*ntp+1][1] = t4[3];
            }
            #pragma unroll
            for (int nt = 0; nt < 4; nt++)
                #pragma unroll
                for (int mt = 0; mt < 2; mt++)
                    mma16(acc[mt][nt], ah[mt], bhf[nt][0], bhf[nt][1]);
        }
        buf ^= 1;
    }

    // ---- epilogue ----
    #pragma unroll
    for (int nt = 0; nt < 4; nt++) {
        int ng0 = n0 + wn * 32 + nt * 8 + 2 * c;
        int which = ng0 >> 8;
        int h = (ng0 >> 5) & 7;
        int e = ng0 & 31;
        int bhI = b * HEADS + h;
        #pragma unroll
        for (int mt = 0; mt < 2; mt++) {
            int p = p0 + wm * 32 + mt * 16 + r;
            float4 a = acc[mt][nt];
            if (which == 2) {
                // V: direct transposed SINGLE fp16 write via shfl_xor(4)
                float px_ = __shfl_xor_sync(0xffffffffu, a.x, 4);
                float py_ = __shfl_xor_sync(0xffffffffu, a.y, 4);
                float pz_ = __shfl_xor_sync(0xffffffffu, a.z, 4);
                float pw_ = __shfl_xor_sync(0xffffffffu, a.w, 4);
                int p0w = p0 + wm*32 + mt*16;
                bool evenr = ((r & 1) == 0);
                int s = r >> 1;
                int j2 = (p0w >> 1) + (evenr ? s : (4 + s));
                float v0e, v1e, v0o, v1o;
                if (evenr) { v0e = a.x; v1e = px_; v0o = a.y; v1o = py_; }
                else       { v0e = pz_; v1e = a.z; v0o = pw_; v1o = a.w; }
                size_t vbase = ((size_t)bhI * 32 + e) * 320;
                g_vth[vbase + j2]       = packhf(v0e, v1e);
                g_vth[vbase + 320 + j2] = packhf(v0o, v1o);
            } else if (which == 0) {
                const float sc = 0.17677669529663687f;
                size_t base = (size_t)bhI * NTOKP * 16 + (e >> 1);
                if (p < NTOK) {
                    unsigned hw, lw; splith2(a.x*sc, a.y*sc, hw, lw);
                    g_qh[base + (size_t)p*16] = hw; g_ql[base + (size_t)p*16] = lw;
                }
                if (p + 8 < NTOK) {
                    unsigned hw, lw; splith2(a.z*sc, a.w*sc, hw, lw);
                    g_qh[base + (size_t)(p+8)*16] = hw; g_ql[base + (size_t)(p+8)*16] = lw;
                }
            } else {
                size_t base = (size_t)bhI * NTOKP * 16 + (e >> 1);
                if (p < NTOK)
                    g_kh[base + (size_t)p*16] = packhf(a.x, a.y);
                if (p + 8 < NTOK)
                    g_kh[base + (size_t)(p+8)*16] = packhf(a.z, a.w);
            }
        }
    }
}

// ============================================================
// Kernel 2: flash attention. Two 64-j tiles per window; V single;
// O epilogue writes SINGLE fp16 (g_oh only). Smem 38912 B.
// ============================================================
#define ATT_KH_W   1280
#define ATT_V_W    1152
#define ATT_VH_OFF 5120
#define ATT_SMEM   ((ATT_VH_OFF + 4*ATT_V_W) * 4)   // 38912 B

__global__ __launch_bounds__(256, 2) void attn_mma() {
    extern __shared__ __align__(16) unsigned asm_[];
    unsigned smb = sptr(asm_);

    int tid = threadIdx.x;
    int wid = tid >> 5, lane = tid & 31;
    int r = lane >> 2, c = lane & 3;

    int q0 = blockIdx.x * 128;
    int bh = blockIdx.y;
    int h = bh & 7;

    int bRow = ((lane >> 4) << 3) | (lane & 7);
    int bSel = ((lane >> 3) & 1) * 4;

    int ckRow = tid >> 2, ckSeg = tid & 3;
    int cvRow = tid >> 3, cvSeg = tid & 7;
    size_t kSrc = ((size_t)bh * NTOKP + ckRow) * 16 + ckSeg * 4;
    size_t vSrc = ((size_t)bh * 32 + cvRow) * 320 + cvSeg * 4;

    auto copy_window = [&](int w, int buf) {
        #pragma unroll
        for (int sub = 0; sub < 2; sub++) {
            int jt = 2*w + sub;
            int slot = buf * 2 + sub;
            cpa16(smb + (slot*ATT_KH_W + ckRow*20 + ckSeg*4) * 4,
                  g_kh + kSrc + (size_t)jt*64*16);
            cpa16(smb + (ATT_VH_OFF + slot*ATT_V_W + cvRow*36 + cvSeg*4) * 4,
                  g_vth + vSrc + jt*32);
        }
    };

    unsigned qh[2][4], ql[2][4];
    {
        const unsigned* qbh = g_qh + (size_t)bh * NTOKP * 16;
        const unsigned* qbl = g_ql + (size_t)bh * NTOKP * 16;
        int pr = q0 + wid * 16 + r;
        #pragma unroll
        for (int kt = 0; kt < 2; kt++) {
            qh[kt][0] = qbh[(size_t)pr*16     + kt*8 + c];
            qh[kt][1] = qbh[(size_t)(pr+8)*16 + kt*8 + c];
            qh[kt][2] = qbh[(size_t)pr*16     + kt*8 + c + 4];
            qh[kt][3] = qbh[(size_t)(pr+8)*16 + kt*8 + c + 4];
            ql[kt][0] = qbl[(size_t)pr*16     + kt*8 + c];
            ql[kt][1] = qbl[(size_t)(pr+8)*16 + kt*8 + c];
            ql[kt][2] = qbl[(size_t)pr*16     + kt*8 + c + 4];
            ql[kt][3] = qbl[(size_t)(pr+8)*16 + kt*8 + c + 4];
        }
    }

    float4 O[4];
    #pragma unroll
    for (int i = 0; i < 4; i++) O[i] = make_float4(0,0,0,0);
    float m0 = -INFINITY, m1 = -INFINITY, l0 = 0.f, l1 = 0.f;

    copy_window(0, 0);
    CP_COMMIT();
    int buf = 0;
    for (int w = 0; w < 5; w++) {
        CP_WAIT0();
        __syncthreads();
        if (w < 4) { copy_window(w + 1, buf ^ 1); CP_COMMIT(); }

        #pragma unroll
        for (int sub = 0; sub < 2; sub++) {
            int j0 = (2*w + sub) * 64;
            int slot = buf * 2 + sub;
            unsigned KhB = smb + slot * ATT_KH_W * 4;
            unsigned VhB = smb + (ATT_VH_OFF + slot * ATT_V_W) * 4;

            float4 acc[8];
            #pragma unroll
            for (int i = 0; i < 8; i++) acc[i] = make_float4(0,0,0,0);
            #pragma unroll
            for (int kt = 0; kt < 2; kt++) {
                unsigned th[4][4];
                #pragma unroll
                for (int ntp = 0; ntp < 4; ntp++) {
                    unsigned off = ((ntp*16 + bRow) * 20 + kt*8 + bSel) * 4u;
                    ldsm4(th[ntp], KhB + off);
                }
                #pragma unroll
                for (int ntp = 0; ntp < 4; ntp++) {
                    mma16(acc[2*ntp  ], qh[kt], th[ntp][0], th[ntp][1]);
                    mma16(acc[2*ntp+1], qh[kt], th[ntp][2], th[ntp][3]);
                    mma16(acc[2*ntp  ], ql[kt], th[ntp][0], th[ntp][1]);
                    mma16(acc[2*ntp+1], ql[kt], th[ntp][2], th[ntp][3]);
                }
            }

            {
                const float* bp = g_bias + ((size_t)(h * NPAD + q0 + wid*16 + r)) * NPAD + j0;
                #pragma unroll
                for (int nt = 0; nt < 8; nt++) {
                    float2 b0v = *(const float2*)&bp[nt*8 + 2*c];
                    float2 b1v = *(const float2*)&bp[8*NPAD + nt*8 + 2*c];
                    acc[nt].x += b0v.x; acc[nt].y += b0v.y;
                    acc[nt].z += b1v.x; acc[nt].w += b1v.y;
                }
                if (j0 + 64 > NTOK) {
                    #pragma unroll
                    for (int nt = 0; nt < 8; nt++) {
                        int jc = j0 + nt*8 + 2*c;
                        if (jc     >= NTOK) { acc[nt].x = -1e30f; acc[nt].z = -1e30f; }
                        if (jc + 1 >= NTOK) { acc[nt].y = -1e30f; acc[nt].w = -1e30f; }
                    }
                }
            }

            float t0 = -INFINITY, t1 = -INFINITY;
            #pragma unroll
            for (int nt = 0; nt < 8; nt++) {
                t0 = fmaxf(t0, fmaxf(acc[nt].x, acc[nt].y));
                t1 = fmaxf(t1, fmaxf(acc[nt].z, acc[nt].w));
            }
            #pragma unroll
            for (int off = 1; off <= 2; off <<= 1) {
                t0 = fmaxf(t0, __shfl_xor_sync(0xffffffffu, t0, off));
                t1 = fmaxf(t1, __shfl_xor_sync(0xffffffffu, t1, off));
            }
            float mn0 = fmaxf(m0, t0), mn1 = fmaxf(m1, t1);
            float cor0 = __expf(m0 - mn0), cor1 = __expf(m1 - mn1);
            float s0 = 0.f, s1 = 0.f;
            #pragma unroll
            for (int nt = 0; nt < 8; nt++) {
                acc[nt].x = __expf(acc[nt].x - mn0);
                acc[nt].y = __expf(acc[nt].y - mn0);
                acc[nt].z = __expf(acc[nt].z - mn1);
                acc[nt].w = __expf(acc[nt].w - mn1);
                s0 += acc[nt].x + acc[nt].y;
                s1 += acc[nt].z + acc[nt].w;
            }
            #pragma unroll
            for (int off = 1; off <= 2; off <<= 1) {
                s0 += __shfl_xor_sync(0xffffffffu, s0, off);
                s1 += __shfl_xor_sync(0xffffffffu, s1, off);
            }
            l0 = l0 * cor0 + s0;  m0 = mn0;
            l1 = l1 * cor1 + s1;  m1 = mn1;
            #pragma unroll
            for (int i = 0; i < 4; i++) {
                O[i].x *= cor0; O[i].y *= cor0;
                O[i].z *= cor1; O[i].w *= cor1;
            }

            #pragma unroll
            for (int kt = 0; kt < 4; kt++) {
                unsigned ph[4];
                ph[0] = packhf(acc[2*kt  ].x, acc[2*kt  ].y);
                ph[1] = packhf(acc[2*kt  ].z, acc[2*kt  ].w);
                ph[2] = packhf(acc[2*kt+1].x, acc[2*kt+1].y);
                ph[3] = packhf(acc[2*kt+1].z, acc[2*kt+1].w);
                #pragma unroll
                for (int ntp = 0; ntp < 2; ntp++) {
                    unsigned off = ((ntp*16 + bRow) * 36 + kt*8 + bSel) * 4u;
                    unsigned th[4];
                    ldsm4(th, VhB + off);
                    mma16(O[2*ntp  ], ph, th[0], th[1]);
                    mma16(O[2*ntp+1], ph, th[2], th[3]);
                }
            }
        }
        buf ^= 1;
    }

    // epilogue: O SINGLE fp16 -> g_oh
    float inv0 = 1.f / l0, inv1 = 1.f / l1;
    size_t ob = (size_t)(bh >> 3) * NTOKP * 128 + h * 16;
    #pragma unroll
    for (int nt = 0; nt < 4; nt++) {
        int w2 = nt * 4 + c;
        int p = q0 + wid * 16 + r;
        if (p < NTOK)
            g_oh[ob + (size_t)p*128 + w2] = packhf(O[nt].x * inv0, O[nt].y * inv0);
        if (p + 8 < NTOK)
            g_oh[ob + (size_t)(p+8)*128 + w2] = packhf(O[nt].z * inv1, O[nt].w * inv1);
    }
}

// ============================================================
// Kernel 3: output projection — plain fp16 (O single x w single).
// Stage: Ah[128][20] @0 | Bh[64][20] @2560 = 3840 words.
// Smem sized for Cs union (35328 B).
// ============================================================
#define STG_O 3840
#define OUT_CS_WORDS (128*69)              // 8832 > 2*3840
#define OUT_SMEM (OUT_CS_WORDS*4)          // 35328 B

__global__ __launch_bounds__(256, 3) void out_mma(float* __restrict__ out) {
    extern __shared__ __align__(16) unsigned osm[];
    float (*Cs)[69] = (float(*)[69])osm;

    int b  = blockIdx.z;
    int p0 = blockIdx.x * 128;
    int n0 = blockIdx.y * 64;
    int tid = threadIdx.x;
    int wid = tid >> 5, lane = tid & 31;
    int wm = wid & 3, wn = wid >> 2;
    int r = lane >> 2, c = lane & 3;
    unsigned smb = sptr(osm);

    float4 acc[2][4];
    #pragma unroll
    for (int i = 0; i < 2; i++)
        #pragma unroll
        for (int j = 0; j < 4; j++) acc[i][j] = make_float4(0,0,0,0);

    int aRow = lane & 15;
    int aSel = (lane >> 4) * 4;
    int bRow = ((lane >> 4) << 3) | (lane & 7);
    int bSel = ((lane >> 3) & 1) * 4;

    int caRow = tid >> 1, caHalf = tid & 1;
    int cbRow = tid >> 2, cbSeg = tid & 3;
    size_t aSrc = ((size_t)b * NTOKP + p0 + caRow) * 128 + caHalf * 8;
    size_t bSrc = (size_t)(n0 + cbRow) * 128 + cbSeg * 4;

    auto copy_slab = [&](int slab, int buf) {
        unsigned sb = smb + buf * STG_O * 4;
        unsigned dA = sb + (caRow*20 + caHalf*8) * 4;
        const unsigned* sh = g_oh + aSrc + slab*16;
        cpa16(dA,      sh);
        cpa16(dA + 16, sh + 4);
        unsigned dB = sb + (2560 + cbRow*20 + cbSeg*4) * 4;
        cpa16(dB, g_woh + bSrc + slab*16);
    };

    copy_slab(0, 0);
    CP_COMMIT();
    int buf = 0;
    for (int s = 0; s < 8; s++) {
        CP_WAIT0();
        __syncthreads();
        if (s < 7) { copy_slab(s + 1, buf ^ 1); CP_COMMIT(); }

        unsigned AhB = smb + buf * STG_O * 4;
        unsigned BhB = AhB + 2560 * 4;
        #pragma unroll
        for (int ktl = 0; ktl < 2; ktl++) {
            unsigned ah[2][4];
            #pragma unroll
            for (int mt = 0; mt < 2; mt++) {
                unsigned off = ((wm*32 + mt*16 + aRow) * 20 + ktl*8 + aSel) * 4u;
                ldsm4(ah[mt], AhB + off);
            }
            unsigned bhf[4][2];
            #pragma unroll
            for (int ntp = 0; ntp < 2; ntp++) {
                unsigned off = ((wn*32 + ntp*16 + bRow) * 20 + ktl*8 + bSel) * 4u;
                unsigned t4[4];
                ldsm4(t4, BhB + off);
                bhf[2*ntp][0] = t4[0]; bhf[2*ntp][1] = t4[1];
                bhf[2*ntp+1][0] = t4[2]; bhf[2*ntp+1][1] = t4[3];
            }
            #pragma unroll
            for (int nt = 0; nt < 4; nt++)
                #pragma unroll
                for (int mt = 0; mt < 2; mt++)
                    mma16(acc[mt][nt], ah[mt], bhf[nt][0], bhf[nt][1]);
        }
        buf ^= 1;
    }

    __syncthreads();

    #pragma unroll
    for (int mt = 0; mt < 2; mt++) {
        int m = wm * 32 + mt * 16 + r;
        #pragma unroll
        for (int nt = 0; nt < 4; nt++) {
            int n = wn * 32 + nt * 8 + 2 * c;
            Cs[m    ][n    ] = acc[mt][nt].x;
            Cs[m    ][n + 1] = acc[mt][nt].y;
            Cs[m + 8][n    ] = acc[mt][nt].z;
            Cs[m + 8][n + 1] = acc[mt][nt].w;
        }
    }
    __syncthreads();

    #pragma unroll
    for (int it = 0; it < 32; it++) {
        int idx = it * 256 + tid;
        int n = idx >> 7;
        int m = idx & 127;
        int p = p0 + m;
        if (p < NTOK)
            out[((size_t)b * DD + n0 + n) * NTOK + p] = Cs[m][n];
    }
}

// ============================================================
extern "C" void kernel_launch(void* const* d_in, const int* in_sizes, int n_in,
                              void* d_out, int out_size) {
    const float* x          = (const float*)d_in[0];
    const float* w_qkv      = (const float*)d_in[1];
    const float* w_out      = (const float*)d_in[2];
    const float* bias_table = (const float*)d_in[3];
    const int*   rel        = (const int*)d_in[4];
    float* out = (float*)d_out;

    cudaFuncSetAttribute(qkv_mma, cudaFuncAttributeMaxDynamicSharedMemorySize,
                         QKV_SMEM);
    cudaFuncSetAttribute(attn_mma, cudaFuncAttributeMaxDynamicSharedMemorySize,
                         ATT_SMEM);
    cudaFuncSetAttribute(out_mma, cudaFuncAttributeMaxDynamicSharedMemorySize,
                         OUT_SMEM);

    prep_all<<<PREP_GRID, 256>>>(x, w_qkv, w_out, bias_table, rel);
    qkv_mma<<<dim3(5, 12, BB), 256, QKV_SMEM>>>();
    attn_mma<<<dim3(5, NBH), 256, ATT_SMEM>>>();
    out_mma<<<dim3(5, 4, BB), 256, OUT_SMEM>>>(out);
}